// round 12
// baseline (speedup 1.0000x reference)
#include <cuda_runtime.h>
#include <cuda_fp16.h>
#include <math.h>

#define N_NODES 100000
#define E_EDGES 800000
#define ET (E_EDGES + N_NODES)   // edges + self loops = 900000
#define IN_CH 128
#define HID 32
#define HEADS 8
#define C1 (HEADS * HID)          // 256
#define OUT_CH 40
#define NEG_SLOPE 0.2f

// ---------------- scratch (device globals; no allocation allowed) ----------
__device__ float  g_xp1[N_NODES * C1];
__device__ __half g_xp1h[N_NODES * C1];   // fp16 mirror for the edge gather
__device__ float  g_h[N_NODES * C1];
__device__ float  g_xp2[N_NODES * OUT_CH];
__device__ float  g_as1[N_NODES * HEADS];
__device__ float  g_ad1[N_NODES * HEADS];
__device__ float  g_as2[N_NODES];
__device__ float  g_ad2[N_NODES];

__device__ int g_deg[N_NODES];
__device__ int g_rowstart[N_NODES + 1];
__device__ int g_cursor[N_NODES];
__device__ int g_csrc[ET];

__device__ __forceinline__ float leaky(float x) {
    return x > 0.0f ? x : NEG_SLOPE * x;
}

// ================= CSR build ================================================
__global__ void zero_kernel() {
    int i = blockIdx.x * blockDim.x + threadIdx.x;
    if (i < N_NODES) g_deg[i] = 0;
}

__global__ void hist_kernel(const int* __restrict__ ei) {
    int e = blockIdx.x * blockDim.x + threadIdx.x;
    if (e >= ET) return;
    int dst = (e < E_EDGES) ? ei[E_EDGES + e] : e - E_EDGES;
    atomicAdd(&g_deg[dst], 1);
}

__global__ void scan_kernel() {
    __shared__ int sums[1024];
    const int t = threadIdx.x;
    const int CH = (N_NODES + 1023) / 1024;
    int lo = t * CH;
    int hi = lo + CH; if (hi > N_NODES) hi = N_NODES;
    int s = 0;
    for (int i = lo; i < hi; i++) s += g_deg[i];
    sums[t] = s;
    __syncthreads();
    for (int o = 1; o < 1024; o <<= 1) {
        int u = (t >= o) ? sums[t - o] : 0;
        __syncthreads();
        sums[t] += u;
        __syncthreads();
    }
    int run = sums[t] - s;
    for (int i = lo; i < hi; i++) {
        g_rowstart[i] = run;
        g_cursor[i]   = run;
        run += g_deg[i];
    }
    if (t == 0) g_rowstart[N_NODES] = ET;
}

__global__ void scatter_kernel(const int* __restrict__ ei) {
    int e = blockIdx.x * blockDim.x + threadIdx.x;
    if (e >= ET) return;
    int src, dst;
    if (e < E_EDGES) { src = ei[e]; dst = ei[E_EDGES + e]; }
    else             { src = dst = e - E_EDGES; }
    int pos = atomicAdd(&g_cursor[dst], 1);
    g_csrc[pos] = src;
}

// ================= tf32 helpers =============================================
__device__ __forceinline__ unsigned tf32_of(float x) {
    unsigned r;
    asm("cvt.rna.tf32.f32 %0, %1;" : "=r"(r) : "f"(x));
    return r;
}
__device__ __forceinline__ void tf32_split(float x, unsigned& hi, unsigned& lo) {
    hi = tf32_of(x);
    float lo_f = x - __uint_as_float(hi);
    lo = tf32_of(lo_f);
}
__device__ __forceinline__ void tf32_split_f(float x, float& hi, float& lo) {
    unsigned h, l;
    tf32_split(x, h, l);
    hi = __uint_as_float(h);
    lo = __uint_as_float(l);
}
__device__ __forceinline__ void mma_tf32(float* d, const unsigned* a, const unsigned* b) {
    asm volatile(
        "mma.sync.aligned.m16n8k8.row.col.f32.tf32.tf32.f32 "
        "{%0,%1,%2,%3}, {%4,%5,%6,%7}, {%8,%9}, {%0,%1,%2,%3};"
        : "+f"(d[0]), "+f"(d[1]), "+f"(d[2]), "+f"(d[3])
        : "r"(a[0]), "r"(a[1]), "r"(a[2]), "r"(a[3]), "r"(b[0]), "r"(b[1]));
}
__device__ __forceinline__ float quad_reduce(float v) {
    v += __shfl_xor_sync(0xffffffffu, v, 1);
    v += __shfl_xor_sync(0xffffffffu, v, 2);
    return v;
}

#define PAD 136

// ============ GEMM1 (tc tf32x3) + fused attn1 dots ==========================
__global__ __launch_bounds__(256) void sgemm1_tc_kernel(const float* __restrict__ A,
                                                        const float* __restrict__ B,
                                                        float* __restrict__ C,
                                                        const float* __restrict__ att_src,
                                                        const float* __restrict__ att_dst,
                                                        int M) {
    __shared__ __align__(16) float AsH[2][8][PAD];
    __shared__ __align__(16) float AsL[2][8][PAD];
    __shared__ __align__(16) float BsH[2][8][PAD];
    __shared__ __align__(16) float BsL[2][8][PAD];

    const int tid  = threadIdx.x;
    const int wid  = tid >> 5;
    const int lane = tid & 31;
    const int warpM = wid & 3;
    const int warpN = wid >> 2;
    const int rowBase = blockIdx.y * 128;
    const int colBase = blockIdx.x * 128;

    const int r = lane >> 2;
    const int c = lane & 3;

    float acc[2][8][4];
#pragma unroll
    for (int i = 0; i < 2; i++)
#pragma unroll
        for (int j = 0; j < 8; j++)
#pragma unroll
            for (int q = 0; q < 4; q++) acc[i][j][q] = 0.0f;

    const int ar  = tid >> 1;
    const int akq = (tid & 1) * 4;
    const int bk  = tid >> 5;
    const int bnq = (tid & 31) * 4;
    const int gr  = rowBase + ar;

    float4 av, bv;

    av = make_float4(0.f, 0.f, 0.f, 0.f);
    if (gr < M) av = *(const float4*)&A[(long)gr * IN_CH + akq];
    bv = *(const float4*)&B[(long)bk * C1 + colBase + bnq];
    {
        float ah_, al_;
        tf32_split_f(av.x, ah_, al_); AsH[0][akq + 0][ar] = ah_; AsL[0][akq + 0][ar] = al_;
        tf32_split_f(av.y, ah_, al_); AsH[0][akq + 1][ar] = ah_; AsL[0][akq + 1][ar] = al_;
        tf32_split_f(av.z, ah_, al_); AsH[0][akq + 2][ar] = ah_; AsL[0][akq + 2][ar] = al_;
        tf32_split_f(av.w, ah_, al_); AsH[0][akq + 3][ar] = ah_; AsL[0][akq + 3][ar] = al_;
        float4 hv, lv;
        tf32_split_f(bv.x, hv.x, lv.x);
        tf32_split_f(bv.y, hv.y, lv.y);
        tf32_split_f(bv.z, hv.z, lv.z);
        tf32_split_f(bv.w, hv.w, lv.w);
        *(float4*)&BsH[0][bk][bnq] = hv;
        *(float4*)&BsL[0][bk][bnq] = lv;
    }
    __syncthreads();

    int p = 0;
#pragma unroll
    for (int s = 0; s < 16; s++) {
        if (s < 15) {
            int k0 = (s + 1) * 8;
            av = make_float4(0.f, 0.f, 0.f, 0.f);
            if (gr < M) av = *(const float4*)&A[(long)gr * IN_CH + k0 + akq];
            bv = *(const float4*)&B[(long)(k0 + bk) * C1 + colBase + bnq];
        }
        {
            unsigned ah[2][4], al[2][4];
#pragma unroll
            for (int im = 0; im < 2; im++) {
                int mb = warpM * 32 + im * 16;
                ah[im][0] = __float_as_uint(AsH[p][c][mb + r]);
                ah[im][1] = __float_as_uint(AsH[p][c][mb + 8 + r]);
                ah[im][2] = __float_as_uint(AsH[p][4 + c][mb + r]);
                ah[im][3] = __float_as_uint(AsH[p][4 + c][mb + 8 + r]);
                al[im][0] = __float_as_uint(AsL[p][c][mb + r]);
                al[im][1] = __float_as_uint(AsL[p][c][mb + 8 + r]);
                al[im][2] = __float_as_uint(AsL[p][4 + c][mb + r]);
                al[im][3] = __float_as_uint(AsL[p][4 + c][mb + 8 + r]);
            }
            unsigned bh[8][2], bl[8][2];
#pragma unroll
            for (int in = 0; in < 8; in++) {
                int nb = warpN * 64 + in * 8 + r;
                bh[in][0] = __float_as_uint(BsH[p][c][nb]);
                bh[in][1] = __float_as_uint(BsH[p][4 + c][nb]);
                bl[in][0] = __float_as_uint(BsL[p][c][nb]);
                bl[in][1] = __float_as_uint(BsL[p][4 + c][nb]);
            }
#pragma unroll
            for (int im = 0; im < 2; im++)
#pragma unroll
                for (int in = 0; in < 8; in++) {
                    mma_tf32(acc[im][in], al[im], bh[in]);
                    mma_tf32(acc[im][in], ah[im], bl[in]);
                    mma_tf32(acc[im][in], ah[im], bh[in]);
                }
        }
        if (s < 15) {
            p ^= 1;
            float ah_, al_;
            tf32_split_f(av.x, ah_, al_); AsH[p][akq + 0][ar] = ah_; AsL[p][akq + 0][ar] = al_;
            tf32_split_f(av.y, ah_, al_); AsH[p][akq + 1][ar] = ah_; AsL[p][akq + 1][ar] = al_;
            tf32_split_f(av.z, ah_, al_); AsH[p][akq + 2][ar] = ah_; AsL[p][akq + 2][ar] = al_;
            tf32_split_f(av.w, ah_, al_); AsH[p][akq + 3][ar] = ah_; AsL[p][akq + 3][ar] = al_;
            float4 hv, lv;
            tf32_split_f(bv.x, hv.x, lv.x);
            tf32_split_f(bv.y, hv.y, lv.y);
            tf32_split_f(bv.z, hv.z, lv.z);
            tf32_split_f(bv.w, hv.w, lv.w);
            *(float4*)&BsH[p][bk][bnq] = hv;
            *(float4*)&BsL[p][bk][bnq] = lv;
            __syncthreads();
        }
    }

    // epilogue: fp32 C + fp16 mirror + fused attention dots (exclusive owner
    // per (row, head) -> plain stores, no atomics, no zero-init needed)
#pragma unroll
    for (int im = 0; im < 2; im++) {
        int row0 = rowBase + warpM * 32 + im * 16 + r;
        int row1 = row0 + 8;
        float s0[2] = {0.f, 0.f}, d0[2] = {0.f, 0.f};
        float s1[2] = {0.f, 0.f}, d1[2] = {0.f, 0.f};
#pragma unroll
        for (int in = 0; in < 8; in++) {
            int col = colBase + warpN * 64 + in * 8 + 2 * c;
            float w0 = att_src[col], w1 = att_src[col + 1];
            float v0 = att_dst[col], v1 = att_dst[col + 1];
            int hp = in >> 2;
            s0[hp] += acc[im][in][0] * w0 + acc[im][in][1] * w1;
            d0[hp] += acc[im][in][0] * v0 + acc[im][in][1] * v1;
            s1[hp] += acc[im][in][2] * w0 + acc[im][in][3] * w1;
            d1[hp] += acc[im][in][2] * v0 + acc[im][in][3] * v1;
            if (row0 < M) {
                float2 v = make_float2(acc[im][in][0], acc[im][in][1]);
                *(float2*)&C[(long)row0 * C1 + col] = v;
                *(__half2*)&g_xp1h[(long)row0 * C1 + col] = __float22half2_rn(v);
            }
            if (row1 < M) {
                float2 v = make_float2(acc[im][in][2], acc[im][in][3]);
                *(float2*)&C[(long)row1 * C1 + col] = v;
                *(__half2*)&g_xp1h[(long)row1 * C1 + col] = __float22half2_rn(v);
            }
        }
#pragma unroll
        for (int hp = 0; hp < 2; hp++) {
            s0[hp] = quad_reduce(s0[hp]); d0[hp] = quad_reduce(d0[hp]);
            s1[hp] = quad_reduce(s1[hp]); d1[hp] = quad_reduce(d1[hp]);
        }
        if (c == 0) {
            int hbase = (colBase >> 5) + warpN * 2;
#pragma unroll
            for (int hp = 0; hp < 2; hp++) {
                if (row0 < M) {
                    g_as1[row0 * 8 + hbase + hp] = s0[hp];
                    g_ad1[row0 * 8 + hbase + hp] = d0[hp];
                }
                if (row1 < M) {
                    g_as1[row1 * 8 + hbase + hp] = s1[hp];
                    g_ad1[row1 * 8 + hbase + hp] = d1[hp];
                }
            }
        }
    }
}

// ============ GEMM2 (tc tf32x3) + fused attn2 dots ==========================
__global__ __launch_bounds__(256) void sgemm2_tc_kernel(const float* __restrict__ A,
                                                        const float* __restrict__ B,
                                                        float* __restrict__ C,
                                                        const float* __restrict__ att_src,
                                                        const float* __restrict__ att_dst,
                                                        int M) {
    __shared__ __align__(16) float As[2][16][PAD];
    __shared__ float BsH[2][16][40];
    __shared__ float BsL[2][16][40];

    const int tid  = threadIdx.x;
    const int wid  = tid >> 5;
    const int lane = tid & 31;
    const int rowBase = blockIdx.x * 128;
    const int r = lane >> 2;
    const int c = lane & 3;

    float acc[5][4];
#pragma unroll
    for (int j = 0; j < 5; j++)
#pragma unroll
        for (int q = 0; q < 4; q++) acc[j][q] = 0.0f;

    float4 avs[2];
    float  bsc[3];

#pragma unroll
    for (int t = 0; t < 2; t++) {
        int q = tid + t * 256;
        int ar = q >> 2, akq = q & 3;
        int gr = rowBase + ar;
        avs[t] = make_float4(0.f, 0.f, 0.f, 0.f);
        if (gr < M) avs[t] = *(const float4*)&A[(long)gr * C1 + akq * 4];
    }
#pragma unroll
    for (int t = 0; t < 3; t++) {
        int idx = tid + t * 256;
        bsc[t] = (idx < 16 * 40) ? B[(long)(idx / 40) * OUT_CH + idx % 40] : 0.f;
    }
#pragma unroll
    for (int t = 0; t < 2; t++) {
        int q = tid + t * 256;
        int ar = q >> 2, akq = q & 3;
        As[0][akq * 4 + 0][ar] = avs[t].x;
        As[0][akq * 4 + 1][ar] = avs[t].y;
        As[0][akq * 4 + 2][ar] = avs[t].z;
        As[0][akq * 4 + 3][ar] = avs[t].w;
    }
#pragma unroll
    for (int t = 0; t < 3; t++) {
        int idx = tid + t * 256;
        if (idx < 16 * 40) {
            float h_, l_;
            tf32_split_f(bsc[t], h_, l_);
            BsH[0][idx / 40][idx % 40] = h_;
            BsL[0][idx / 40][idx % 40] = l_;
        }
    }
    __syncthreads();

    int p = 0;
#pragma unroll
    for (int s = 0; s < 16; s++) {
        if (s < 15) {
            int k0 = (s + 1) * 16;
#pragma unroll
            for (int t = 0; t < 2; t++) {
                int q = tid + t * 256;
                int ar = q >> 2, akq = q & 3;
                int gr = rowBase + ar;
                avs[t] = make_float4(0.f, 0.f, 0.f, 0.f);
                if (gr < M) avs[t] = *(const float4*)&A[(long)gr * C1 + k0 + akq * 4];
            }
#pragma unroll
            for (int t = 0; t < 3; t++) {
                int idx = tid + t * 256;
                bsc[t] = (idx < 16 * 40) ? B[(long)(k0 + idx / 40) * OUT_CH + idx % 40] : 0.f;
            }
        }
#pragma unroll
        for (int kk = 0; kk < 16; kk += 8) {
            unsigned ah[4], al[4];
            {
                int mb = wid * 16;
                tf32_split(As[p][kk + c][mb + r],         ah[0], al[0]);
                tf32_split(As[p][kk + c][mb + 8 + r],     ah[1], al[1]);
                tf32_split(As[p][kk + 4 + c][mb + r],     ah[2], al[2]);
                tf32_split(As[p][kk + 4 + c][mb + 8 + r], ah[3], al[3]);
            }
#pragma unroll
            for (int in = 0; in < 5; in++) {
                int nb = in * 8 + r;
                unsigned bh[2], bl[2];
                bh[0] = __float_as_uint(BsH[p][kk + c][nb]);
                bh[1] = __float_as_uint(BsH[p][kk + 4 + c][nb]);
                bl[0] = __float_as_uint(BsL[p][kk + c][nb]);
                bl[1] = __float_as_uint(BsL[p][kk + 4 + c][nb]);
                mma_tf32(acc[in], al, bh);
                mma_tf32(acc[in], ah, bl);
                mma_tf32(acc[in], ah, bh);
            }
        }
        if (s < 15) {
            p ^= 1;
#pragma unroll
            for (int t = 0; t < 2; t++) {
                int q = tid + t * 256;
                int ar = q >> 2, akq = q & 3;
                As[p][akq * 4 + 0][ar] = avs[t].x;
                As[p][akq * 4 + 1][ar] = avs[t].y;
                As[p][akq * 4 + 2][ar] = avs[t].z;
                As[p][akq * 4 + 3][ar] = avs[t].w;
            }
#pragma unroll
            for (int t = 0; t < 3; t++) {
                int idx = tid + t * 256;
                if (idx < 16 * 40) {
                    float h_, l_;
                    tf32_split_f(bsc[t], h_, l_);
                    BsH[p][idx / 40][idx % 40] = h_;
                    BsL[p][idx / 40][idx % 40] = l_;
                }
            }
            __syncthreads();
        }
    }

    // epilogue: C + fused attn2 dots
    {
        int row0 = rowBase + wid * 16 + r;
        int row1 = row0 + 8;
        float s0 = 0.f, d0 = 0.f, s1 = 0.f, d1 = 0.f;
#pragma unroll
        for (int in = 0; in < 5; in++) {
            int col = in * 8 + 2 * c;
            float w0 = att_src[col], w1 = att_src[col + 1];
            float v0 = att_dst[col], v1 = att_dst[col + 1];
            s0 += acc[in][0] * w0 + acc[in][1] * w1;
            d0 += acc[in][0] * v0 + acc[in][1] * v1;
            s1 += acc[in][2] * w0 + acc[in][3] * w1;
            d1 += acc[in][2] * v0 + acc[in][3] * v1;
            if (row0 < M)
                *(float2*)&C[(long)row0 * OUT_CH + col] = make_float2(acc[in][0], acc[in][1]);
            if (row1 < M)
                *(float2*)&C[(long)row1 * OUT_CH + col] = make_float2(acc[in][2], acc[in][3]);
        }
        s0 = quad_reduce(s0); d0 = quad_reduce(d0);
        s1 = quad_reduce(s1); d1 = quad_reduce(d1);
        if (c == 0) {
            if (row0 < M) { g_as2[row0] = s0; g_ad2[row0] = d0; }
            if (row1 < M) { g_as2[row1] = s1; g_ad2[row1] = d1; }
        }
    }
}

// ------- layer-1 aggregation: online softmax single pass, fp16 gather -------
__global__ __launch_bounds__(256) void agg1_kernel(const float* __restrict__ b1) {
    int n = (blockIdx.x * blockDim.x + threadIdx.x) >> 5;
    int lane = threadIdx.x & 31;
    if (n >= N_NODES) return;
    const int start = g_rowstart[n];
    const int end   = g_rowstart[n + 1];
    const float adv = g_ad1[n * 8 + (lane & 7)];
    const int hsel = lane >> 2;

    float m = -INFINITY, z = 0.f;
    float2 acc4[4];
#pragma unroll
    for (int q = 0; q < 4; q++) acc4[q] = make_float2(0.f, 0.f);

    int s = g_csrc[start];
    for (int i = start; i < end; i++) {
        int s_next = (i + 1 < end) ? g_csrc[i + 1] : s;
        float a_s = (lane < 8) ? g_as1[s * 8 + lane] : 0.f;
        float4 raw = *(const float4*)&g_xp1h[(long)s * C1 + 8 * lane];
        float corr = 1.f, p = 0.f;
        if (lane < 8) {
            float l = leaky(a_s + adv);
            float mn = fmaxf(m, l);
            corr = __expf(m - mn);      // first edge: exp(-inf) = 0
            p = __expf(l - mn);
            z = z * corr + p;
            m = mn;
        }
        float ch = __shfl_sync(0xffffffffu, corr, hsel);
        float ph = __shfl_sync(0xffffffffu, p, hsel);
        const __half2* hp2 = reinterpret_cast<const __half2*>(&raw);
#pragma unroll
        for (int q = 0; q < 4; q++) {
            float2 f = __half22float2(hp2[q]);
            acc4[q].x = acc4[q].x * ch + ph * f.x;
            acc4[q].y = acc4[q].y * ch + ph * f.y;
        }
        s = s_next;
    }

    // finalize: divide, bias, relu -> g_h
    float zh = __shfl_sync(0xffffffffu, z, hsel);
    float zi = 1.0f / (zh + 1e-16f);
    int ch = 8 * lane;
    float4 o0, o1;
    o0.x = fmaxf(acc4[0].x * zi + b1[ch + 0], 0.f);
    o0.y = fmaxf(acc4[0].y * zi + b1[ch + 1], 0.f);
    o0.z = fmaxf(acc4[1].x * zi + b1[ch + 2], 0.f);
    o0.w = fmaxf(acc4[1].y * zi + b1[ch + 3], 0.f);
    o1.x = fmaxf(acc4[2].x * zi + b1[ch + 4], 0.f);
    o1.y = fmaxf(acc4[2].y * zi + b1[ch + 5], 0.f);
    o1.z = fmaxf(acc4[3].x * zi + b1[ch + 6], 0.f);
    o1.w = fmaxf(acc4[3].y * zi + b1[ch + 7], 0.f);
    float* hd = &g_h[(long)n * C1];
    *(float4*)&hd[ch]     = o0;
    *(float4*)&hd[ch + 4] = o1;
}

// -------- layer-2 aggregation (online softmax) + log_softmax ----------------
__global__ __launch_bounds__(256) void agg2_kernel(const float* __restrict__ b2,
                                                   float* __restrict__ out) {
    int n = (blockIdx.x * blockDim.x + threadIdx.x) >> 5;
    int lane = threadIdx.x & 31;
    if (n >= N_NODES) return;
    const int start = g_rowstart[n];
    const int end   = g_rowstart[n + 1];
    const float adn = g_ad2[n];

    float m = -INFINITY, z = 0.f;
    float4 a = make_float4(0.f, 0.f, 0.f, 0.f);

    int s = g_csrc[start];
    for (int i = start; i < end; i++) {
        int s_next = (i + 1 < end) ? g_csrc[i + 1] : s;
        float as = g_as2[s];
        float4 xs = make_float4(0.f, 0.f, 0.f, 0.f);
        if (lane < 10) xs = *(const float4*)&g_xp2[(long)s * OUT_CH + 4 * lane];
        float l = leaky(as + adn);
        float mn = fmaxf(m, l);
        float corr = __expf(m - mn);
        float p = __expf(l - mn);
        z = z * corr + p;
        m = mn;
        a.x = a.x * corr + p * xs.x;
        a.y = a.y * corr + p * xs.y;
        a.z = a.z * corr + p * xs.z;
        a.w = a.w * corr + p * xs.w;
        s = s_next;
    }
    float zi = 1.0f / (z + 1e-16f);

    float x0 = -INFINITY, x1 = -INFINITY, x2 = -INFINITY, x3 = -INFINITY;
    if (lane < 10) {
        int ch = 4 * lane;
        x0 = a.x * zi + b2[ch + 0];
        x1 = a.y * zi + b2[ch + 1];
        x2 = a.z * zi + b2[ch + 2];
        x3 = a.w * zi + b2[ch + 3];
    }
    float mx = fmaxf(fmaxf(x0, x1), fmaxf(x2, x3));
#pragma unroll
    for (int o = 16; o > 0; o >>= 1) mx = fmaxf(mx, __shfl_xor_sync(0xffffffffu, mx, o));
    float se = 0.f;
    if (lane < 10)
        se = __expf(x0 - mx) + __expf(x1 - mx) + __expf(x2 - mx) + __expf(x3 - mx);
#pragma unroll
    for (int o = 16; o > 0; o >>= 1) se += __shfl_xor_sync(0xffffffffu, se, o);
    float lse = mx + logf(se);
    if (lane < 10) {
        float4 o4 = make_float4(x0 - lse, x1 - lse, x2 - lse, x3 - lse);
        *(float4*)&out[(long)n * OUT_CH + 4 * lane] = o4;
    }
}

// ---------------- launch ----------------------------------------------------
extern "C" void kernel_launch(void* const* d_in, const int* in_sizes, int n_in,
                              void* d_out, int out_size) {
    const float* x        = (const float*)d_in[0];
    const int*   ei       = (const int*)d_in[1];
    const float* W1       = (const float*)d_in[2];
    const float* att_src1 = (const float*)d_in[3];
    const float* att_dst1 = (const float*)d_in[4];
    const float* b1       = (const float*)d_in[5];
    const float* W2       = (const float*)d_in[6];
    const float* att_src2 = (const float*)d_in[7];
    const float* att_dst2 = (const float*)d_in[8];
    const float* b2       = (const float*)d_in[9];
    float*       out      = (float*)d_out;

    float* xp1 = nullptr; float* h = nullptr; float* xp2 = nullptr;
    cudaGetSymbolAddress((void**)&xp1, g_xp1);
    cudaGetSymbolAddress((void**)&h,   g_h);
    cudaGetSymbolAddress((void**)&xp2, g_xp2);

    // CSR build (shared by both layers)
    zero_kernel<<<(N_NODES + 255) / 256, 256>>>();
    hist_kernel<<<(ET + 255) / 256, 256>>>(ei);
    scan_kernel<<<1, 1024>>>();
    scatter_kernel<<<(ET + 255) / 256, 256>>>(ei);

    // layer 1 (attn1 fused into GEMM1 epilogue)
    {
        dim3 grid(C1 / 128, (N_NODES + 127) / 128);
        sgemm1_tc_kernel<<<grid, 256>>>(x, W1, xp1, att_src1, att_dst1, N_NODES);
    }
    agg1_kernel<<<(N_NODES * 32 + 255) / 256, 256>>>(b1);

    // layer 2 (attn2 fused into GEMM2 epilogue)
    sgemm2_tc_kernel<<<(N_NODES + 127) / 128, 256>>>(h, W2, xp2, att_src2, att_dst2, N_NODES);
    agg2_kernel<<<(N_NODES * 32 + 255) / 256, 256>>>(b2, out);
}

// round 13
// speedup vs baseline: 1.0511x; 1.0511x over previous
#include <cuda_runtime.h>
#include <cuda_fp16.h>
#include <math.h>

#define N_NODES 100000
#define E_EDGES 800000
#define ET (E_EDGES + N_NODES)   // edges + self loops = 900000
#define IN_CH 128
#define HID 32
#define HEADS 8
#define C1 (HEADS * HID)          // 256
#define OUT_CH 40
#define NEG_SLOPE 0.2f

// ---------------- scratch (device globals; no allocation allowed) ----------
__device__ __half g_xp1h[N_NODES * C1];     // fp16 xp1 (only consumer of GEMM1)
__device__ float  g_h[N_NODES * C1];
__device__ float  g_xp2[N_NODES * OUT_CH];  // fp32 xp2 (attn dots use registers)
__device__ __half g_xp2h[N_NODES * OUT_CH]; // fp16 mirror for agg2 gather
__device__ float  g_as1[N_NODES * HEADS];
__device__ float  g_ad1[N_NODES * HEADS];
__device__ float  g_as2[N_NODES];
__device__ float  g_ad2[N_NODES];

__device__ int g_deg[N_NODES];
__device__ int g_rowstart[N_NODES + 1];
__device__ int g_cursor[N_NODES];
__device__ int g_csrc[ET];

__device__ __forceinline__ float leaky(float x) {
    return x > 0.0f ? x : NEG_SLOPE * x;
}

// ================= CSR build ================================================
__global__ void zero_kernel() {
    int i = blockIdx.x * blockDim.x + threadIdx.x;
    if (i < N_NODES) g_deg[i] = 0;
}

__global__ void hist_kernel(const int* __restrict__ ei) {
    int e = blockIdx.x * blockDim.x + threadIdx.x;
    if (e >= ET) return;
    int dst = (e < E_EDGES) ? ei[E_EDGES + e] : e - E_EDGES;
    atomicAdd(&g_deg[dst], 1);
}

__global__ void scan_kernel() {
    __shared__ int sums[1024];
    const int t = threadIdx.x;
    const int CH = (N_NODES + 1023) / 1024;
    int lo = t * CH;
    int hi = lo + CH; if (hi > N_NODES) hi = N_NODES;
    int s = 0;
    for (int i = lo; i < hi; i++) s += g_deg[i];
    sums[t] = s;
    __syncthreads();
    for (int o = 1; o < 1024; o <<= 1) {
        int u = (t >= o) ? sums[t - o] : 0;
        __syncthreads();
        sums[t] += u;
        __syncthreads();
    }
    int run = sums[t] - s;
    for (int i = lo; i < hi; i++) {
        g_rowstart[i] = run;
        g_cursor[i]   = run;
        run += g_deg[i];
    }
    if (t == 0) g_rowstart[N_NODES] = ET;
}

__global__ void scatter_kernel(const int* __restrict__ ei) {
    int e = blockIdx.x * blockDim.x + threadIdx.x;
    if (e >= ET) return;
    int src, dst;
    if (e < E_EDGES) { src = ei[e]; dst = ei[E_EDGES + e]; }
    else             { src = dst = e - E_EDGES; }
    int pos = atomicAdd(&g_cursor[dst], 1);
    g_csrc[pos] = src;
}

// ================= tf32 helpers =============================================
__device__ __forceinline__ unsigned tf32_of(float x) {
    unsigned r;
    asm("cvt.rna.tf32.f32 %0, %1;" : "=r"(r) : "f"(x));
    return r;
}
__device__ __forceinline__ void tf32_split(float x, unsigned& hi, unsigned& lo) {
    hi = tf32_of(x);
    float lo_f = x - __uint_as_float(hi);
    lo = tf32_of(lo_f);
}
__device__ __forceinline__ void tf32_split_f(float x, float& hi, float& lo) {
    unsigned h, l;
    tf32_split(x, h, l);
    hi = __uint_as_float(h);
    lo = __uint_as_float(l);
}
__device__ __forceinline__ void mma_tf32(float* d, const unsigned* a, const unsigned* b) {
    asm volatile(
        "mma.sync.aligned.m16n8k8.row.col.f32.tf32.tf32.f32 "
        "{%0,%1,%2,%3}, {%4,%5,%6,%7}, {%8,%9}, {%0,%1,%2,%3};"
        : "+f"(d[0]), "+f"(d[1]), "+f"(d[2]), "+f"(d[3])
        : "r"(a[0]), "r"(a[1]), "r"(a[2]), "r"(a[3]), "r"(b[0]), "r"(b[1]));
}
__device__ __forceinline__ float quad_reduce(float v) {
    v += __shfl_xor_sync(0xffffffffu, v, 1);
    v += __shfl_xor_sync(0xffffffffu, v, 2);
    return v;
}

#define PAD 136

// ============ GEMM1 (tc tf32x3) + fused attn1 dots, fp16-only output ========
__global__ __launch_bounds__(256) void sgemm1_tc_kernel(const float* __restrict__ A,
                                                        const float* __restrict__ B,
                                                        const float* __restrict__ att_src,
                                                        const float* __restrict__ att_dst,
                                                        int M) {
    __shared__ __align__(16) float AsH[2][8][PAD];
    __shared__ __align__(16) float AsL[2][8][PAD];
    __shared__ __align__(16) float BsH[2][8][PAD];
    __shared__ __align__(16) float BsL[2][8][PAD];

    const int tid  = threadIdx.x;
    const int wid  = tid >> 5;
    const int lane = tid & 31;
    const int warpM = wid & 3;
    const int warpN = wid >> 2;
    const int rowBase = blockIdx.y * 128;
    const int colBase = blockIdx.x * 128;

    const int r = lane >> 2;
    const int c = lane & 3;

    float acc[2][8][4];
#pragma unroll
    for (int i = 0; i < 2; i++)
#pragma unroll
        for (int j = 0; j < 8; j++)
#pragma unroll
            for (int q = 0; q < 4; q++) acc[i][j][q] = 0.0f;

    const int ar  = tid >> 1;
    const int akq = (tid & 1) * 4;
    const int bk  = tid >> 5;
    const int bnq = (tid & 31) * 4;
    const int gr  = rowBase + ar;

    float4 av, bv;

    av = make_float4(0.f, 0.f, 0.f, 0.f);
    if (gr < M) av = *(const float4*)&A[(long)gr * IN_CH + akq];
    bv = *(const float4*)&B[(long)bk * C1 + colBase + bnq];
    {
        float ah_, al_;
        tf32_split_f(av.x, ah_, al_); AsH[0][akq + 0][ar] = ah_; AsL[0][akq + 0][ar] = al_;
        tf32_split_f(av.y, ah_, al_); AsH[0][akq + 1][ar] = ah_; AsL[0][akq + 1][ar] = al_;
        tf32_split_f(av.z, ah_, al_); AsH[0][akq + 2][ar] = ah_; AsL[0][akq + 2][ar] = al_;
        tf32_split_f(av.w, ah_, al_); AsH[0][akq + 3][ar] = ah_; AsL[0][akq + 3][ar] = al_;
        float4 hv, lv;
        tf32_split_f(bv.x, hv.x, lv.x);
        tf32_split_f(bv.y, hv.y, lv.y);
        tf32_split_f(bv.z, hv.z, lv.z);
        tf32_split_f(bv.w, hv.w, lv.w);
        *(float4*)&BsH[0][bk][bnq] = hv;
        *(float4*)&BsL[0][bk][bnq] = lv;
    }
    __syncthreads();

    int p = 0;
#pragma unroll
    for (int s = 0; s < 16; s++) {
        if (s < 15) {
            int k0 = (s + 1) * 8;
            av = make_float4(0.f, 0.f, 0.f, 0.f);
            if (gr < M) av = *(const float4*)&A[(long)gr * IN_CH + k0 + akq];
            bv = *(const float4*)&B[(long)(k0 + bk) * C1 + colBase + bnq];
        }
        {
            unsigned ah[2][4], al[2][4];
#pragma unroll
            for (int im = 0; im < 2; im++) {
                int mb = warpM * 32 + im * 16;
                ah[im][0] = __float_as_uint(AsH[p][c][mb + r]);
                ah[im][1] = __float_as_uint(AsH[p][c][mb + 8 + r]);
                ah[im][2] = __float_as_uint(AsH[p][4 + c][mb + r]);
                ah[im][3] = __float_as_uint(AsH[p][4 + c][mb + 8 + r]);
                al[im][0] = __float_as_uint(AsL[p][c][mb + r]);
                al[im][1] = __float_as_uint(AsL[p][c][mb + 8 + r]);
                al[im][2] = __float_as_uint(AsL[p][4 + c][mb + r]);
                al[im][3] = __float_as_uint(AsL[p][4 + c][mb + 8 + r]);
            }
            unsigned bh[8][2], bl[8][2];
#pragma unroll
            for (int in = 0; in < 8; in++) {
                int nb = warpN * 64 + in * 8 + r;
                bh[in][0] = __float_as_uint(BsH[p][c][nb]);
                bh[in][1] = __float_as_uint(BsH[p][4 + c][nb]);
                bl[in][0] = __float_as_uint(BsL[p][c][nb]);
                bl[in][1] = __float_as_uint(BsL[p][4 + c][nb]);
            }
#pragma unroll
            for (int im = 0; im < 2; im++)
#pragma unroll
                for (int in = 0; in < 8; in++) {
                    mma_tf32(acc[im][in], al[im], bh[in]);
                    mma_tf32(acc[im][in], ah[im], bl[in]);
                    mma_tf32(acc[im][in], ah[im], bh[in]);
                }
        }
        if (s < 15) {
            p ^= 1;
            float ah_, al_;
            tf32_split_f(av.x, ah_, al_); AsH[p][akq + 0][ar] = ah_; AsL[p][akq + 0][ar] = al_;
            tf32_split_f(av.y, ah_, al_); AsH[p][akq + 1][ar] = ah_; AsL[p][akq + 1][ar] = al_;
            tf32_split_f(av.z, ah_, al_); AsH[p][akq + 2][ar] = ah_; AsL[p][akq + 2][ar] = al_;
            tf32_split_f(av.w, ah_, al_); AsH[p][akq + 3][ar] = ah_; AsL[p][akq + 3][ar] = al_;
            float4 hv, lv;
            tf32_split_f(bv.x, hv.x, lv.x);
            tf32_split_f(bv.y, hv.y, lv.y);
            tf32_split_f(bv.z, hv.z, lv.z);
            tf32_split_f(bv.w, hv.w, lv.w);
            *(float4*)&BsH[p][bk][bnq] = hv;
            *(float4*)&BsL[p][bk][bnq] = lv;
            __syncthreads();
        }
    }

    // epilogue: fp16 mirror only (fp32 xp1 has no readers) + fused attn dots
#pragma unroll
    for (int im = 0; im < 2; im++) {
        int row0 = rowBase + warpM * 32 + im * 16 + r;
        int row1 = row0 + 8;
        float s0[2] = {0.f, 0.f}, d0[2] = {0.f, 0.f};
        float s1[2] = {0.f, 0.f}, d1[2] = {0.f, 0.f};
#pragma unroll
        for (int in = 0; in < 8; in++) {
            int col = colBase + warpN * 64 + in * 8 + 2 * c;
            float w0 = att_src[col], w1 = att_src[col + 1];
            float v0 = att_dst[col], v1 = att_dst[col + 1];
            int hp = in >> 2;
            s0[hp] += acc[im][in][0] * w0 + acc[im][in][1] * w1;
            d0[hp] += acc[im][in][0] * v0 + acc[im][in][1] * v1;
            s1[hp] += acc[im][in][2] * w0 + acc[im][in][3] * w1;
            d1[hp] += acc[im][in][2] * v0 + acc[im][in][3] * v1;
            if (row0 < M)
                *(__half2*)&g_xp1h[(long)row0 * C1 + col] =
                    __float22half2_rn(make_float2(acc[im][in][0], acc[im][in][1]));
            if (row1 < M)
                *(__half2*)&g_xp1h[(long)row1 * C1 + col] =
                    __float22half2_rn(make_float2(acc[im][in][2], acc[im][in][3]));
        }
#pragma unroll
        for (int hp = 0; hp < 2; hp++) {
            s0[hp] = quad_reduce(s0[hp]); d0[hp] = quad_reduce(d0[hp]);
            s1[hp] = quad_reduce(s1[hp]); d1[hp] = quad_reduce(d1[hp]);
        }
        if (c == 0) {
            int hbase = (colBase >> 5) + warpN * 2;
#pragma unroll
            for (int hp = 0; hp < 2; hp++) {
                if (row0 < M) {
                    g_as1[row0 * 8 + hbase + hp] = s0[hp];
                    g_ad1[row0 * 8 + hbase + hp] = d0[hp];
                }
                if (row1 < M) {
                    g_as1[row1 * 8 + hbase + hp] = s1[hp];
                    g_ad1[row1 * 8 + hbase + hp] = d1[hp];
                }
            }
        }
    }
}

// ============ GEMM2 (tc tf32x3) + fused attn2 dots + fp16 mirror ============
__global__ __launch_bounds__(256) void sgemm2_tc_kernel(const float* __restrict__ A,
                                                        const float* __restrict__ B,
                                                        float* __restrict__ C,
                                                        const float* __restrict__ att_src,
                                                        const float* __restrict__ att_dst,
                                                        int M) {
    __shared__ __align__(16) float As[2][16][PAD];
    __shared__ float BsH[2][16][40];
    __shared__ float BsL[2][16][40];

    const int tid  = threadIdx.x;
    const int wid  = tid >> 5;
    const int lane = tid & 31;
    const int rowBase = blockIdx.x * 128;
    const int r = lane >> 2;
    const int c = lane & 3;

    float acc[5][4];
#pragma unroll
    for (int j = 0; j < 5; j++)
#pragma unroll
        for (int q = 0; q < 4; q++) acc[j][q] = 0.0f;

    float4 avs[2];
    float  bsc[3];

#pragma unroll
    for (int t = 0; t < 2; t++) {
        int q = tid + t * 256;
        int ar = q >> 2, akq = q & 3;
        int gr = rowBase + ar;
        avs[t] = make_float4(0.f, 0.f, 0.f, 0.f);
        if (gr < M) avs[t] = *(const float4*)&A[(long)gr * C1 + akq * 4];
    }
#pragma unroll
    for (int t = 0; t < 3; t++) {
        int idx = tid + t * 256;
        bsc[t] = (idx < 16 * 40) ? B[(long)(idx / 40) * OUT_CH + idx % 40] : 0.f;
    }
#pragma unroll
    for (int t = 0; t < 2; t++) {
        int q = tid + t * 256;
        int ar = q >> 2, akq = q & 3;
        As[0][akq * 4 + 0][ar] = avs[t].x;
        As[0][akq * 4 + 1][ar] = avs[t].y;
        As[0][akq * 4 + 2][ar] = avs[t].z;
        As[0][akq * 4 + 3][ar] = avs[t].w;
    }
#pragma unroll
    for (int t = 0; t < 3; t++) {
        int idx = tid + t * 256;
        if (idx < 16 * 40) {
            float h_, l_;
            tf32_split_f(bsc[t], h_, l_);
            BsH[0][idx / 40][idx % 40] = h_;
            BsL[0][idx / 40][idx % 40] = l_;
        }
    }
    __syncthreads();

    int p = 0;
#pragma unroll
    for (int s = 0; s < 16; s++) {
        if (s < 15) {
            int k0 = (s + 1) * 16;
#pragma unroll
            for (int t = 0; t < 2; t++) {
                int q = tid + t * 256;
                int ar = q >> 2, akq = q & 3;
                int gr = rowBase + ar;
                avs[t] = make_float4(0.f, 0.f, 0.f, 0.f);
                if (gr < M) avs[t] = *(const float4*)&A[(long)gr * C1 + k0 + akq * 4];
            }
#pragma unroll
            for (int t = 0; t < 3; t++) {
                int idx = tid + t * 256;
                bsc[t] = (idx < 16 * 40) ? B[(long)(k0 + idx / 40) * OUT_CH + idx % 40] : 0.f;
            }
        }
#pragma unroll
        for (int kk = 0; kk < 16; kk += 8) {
            unsigned ah[4], al[4];
            {
                int mb = wid * 16;
                tf32_split(As[p][kk + c][mb + r],         ah[0], al[0]);
                tf32_split(As[p][kk + c][mb + 8 + r],     ah[1], al[1]);
                tf32_split(As[p][kk + 4 + c][mb + r],     ah[2], al[2]);
                tf32_split(As[p][kk + 4 + c][mb + 8 + r], ah[3], al[3]);
            }
#pragma unroll
            for (int in = 0; in < 5; in++) {
                int nb = in * 8 + r;
                unsigned bh[2], bl[2];
                bh[0] = __float_as_uint(BsH[p][kk + c][nb]);
                bh[1] = __float_as_uint(BsH[p][kk + 4 + c][nb]);
                bl[0] = __float_as_uint(BsL[p][kk + c][nb]);
                bl[1] = __float_as_uint(BsL[p][kk + 4 + c][nb]);
                mma_tf32(acc[in], al, bh);
                mma_tf32(acc[in], ah, bl);
                mma_tf32(acc[in], ah, bh);
            }
        }
        if (s < 15) {
            p ^= 1;
#pragma unroll
            for (int t = 0; t < 2; t++) {
                int q = tid + t * 256;
                int ar = q >> 2, akq = q & 3;
                As[p][akq * 4 + 0][ar] = avs[t].x;
                As[p][akq * 4 + 1][ar] = avs[t].y;
                As[p][akq * 4 + 2][ar] = avs[t].z;
                As[p][akq * 4 + 3][ar] = avs[t].w;
            }
#pragma unroll
            for (int t = 0; t < 3; t++) {
                int idx = tid + t * 256;
                if (idx < 16 * 40) {
                    float h_, l_;
                    tf32_split_f(bsc[t], h_, l_);
                    BsH[p][idx / 40][idx % 40] = h_;
                    BsL[p][idx / 40][idx % 40] = l_;
                }
            }
            __syncthreads();
        }
    }

    // epilogue: fp32 C (for agg2 fallback precision on z path) + fp16 mirror +
    // fused attn2 dots
    {
        int row0 = rowBase + wid * 16 + r;
        int row1 = row0 + 8;
        float s0 = 0.f, d0 = 0.f, s1 = 0.f, d1 = 0.f;
#pragma unroll
        for (int in = 0; in < 5; in++) {
            int col = in * 8 + 2 * c;
            float w0 = att_src[col], w1 = att_src[col + 1];
            float v0 = att_dst[col], v1 = att_dst[col + 1];
            s0 += acc[in][0] * w0 + acc[in][1] * w1;
            d0 += acc[in][0] * v0 + acc[in][1] * v1;
            s1 += acc[in][2] * w0 + acc[in][3] * w1;
            d1 += acc[in][2] * v0 + acc[in][3] * v1;
            if (row0 < M) {
                float2 v = make_float2(acc[in][0], acc[in][1]);
                *(float2*)&C[(long)row0 * OUT_CH + col] = v;
                *(__half2*)&g_xp2h[(long)row0 * OUT_CH + col] = __float22half2_rn(v);
            }
            if (row1 < M) {
                float2 v = make_float2(acc[in][2], acc[in][3]);
                *(float2*)&C[(long)row1 * OUT_CH + col] = v;
                *(__half2*)&g_xp2h[(long)row1 * OUT_CH + col] = __float22half2_rn(v);
            }
        }
        s0 = quad_reduce(s0); d0 = quad_reduce(d0);
        s1 = quad_reduce(s1); d1 = quad_reduce(d1);
        if (c == 0) {
            if (row0 < M) { g_as2[row0] = s0; g_ad2[row0] = d0; }
            if (row1 < M) { g_as2[row1] = s1; g_ad2[row1] = d1; }
        }
    }
}

// ------- layer-1 aggregation: two-pass, fp16 float4 gather ------------------
__global__ __launch_bounds__(256) void agg1_kernel(const float* __restrict__ b1) {
    int n = (blockIdx.x * blockDim.x + threadIdx.x) >> 5;
    int lane = threadIdx.x & 31;
    if (n >= N_NODES) return;
    const int start = g_rowstart[n];
    const int end   = g_rowstart[n + 1];

    const int h   = lane & 7;
    const int grp = lane >> 3;
    const float adv = g_ad1[n * 8 + h];

    // pass 1: per-head max
    float m = -INFINITY;
    for (int i = start + grp; i < end; i += 4) {
        int s = g_csrc[i];
        m = fmaxf(m, leaky(g_as1[s * 8 + h] + adv));
    }
    m = fmaxf(m, __shfl_xor_sync(0xffffffffu, m, 8));
    m = fmaxf(m, __shfl_xor_sync(0xffffffffu, m, 16));

    // pass 2: exp + fp16 float4 gather (lane owns channels 8*lane..8*lane+7)
    float2 acc4[4];
#pragma unroll
    for (int q = 0; q < 4; q++) acc4[q] = make_float2(0.f, 0.f);
    float z = 0.f;
    const int hsel = lane >> 2;
    for (int i = start; i < end; i++) {
        int s = g_csrc[i];
        float p = 0.f;
        if (lane < 8) {
            p = __expf(leaky(g_as1[s * 8 + lane] + adv) - m);
            z += p;
        }
        float4 raw = *(const float4*)&g_xp1h[(long)s * C1 + 8 * lane];
        const __half2* hp = reinterpret_cast<const __half2*>(&raw);
        float ph = __shfl_sync(0xffffffffu, p, hsel);
#pragma unroll
        for (int q = 0; q < 4; q++) {
            float2 f = __half22float2(hp[q]);
            acc4[q].x += ph * f.x;
            acc4[q].y += ph * f.y;
        }
    }

    // finalize: divide, bias, relu -> g_h
    float zh = __shfl_sync(0xffffffffu, z, hsel);
    float zi = 1.0f / (zh + 1e-16f);
    int ch = 8 * lane;
    float4 o0, o1;
    o0.x = fmaxf(acc4[0].x * zi + b1[ch + 0], 0.f);
    o0.y = fmaxf(acc4[0].y * zi + b1[ch + 1], 0.f);
    o0.z = fmaxf(acc4[1].x * zi + b1[ch + 2], 0.f);
    o0.w = fmaxf(acc4[1].y * zi + b1[ch + 3], 0.f);
    o1.x = fmaxf(acc4[2].x * zi + b1[ch + 4], 0.f);
    o1.y = fmaxf(acc4[2].y * zi + b1[ch + 5], 0.f);
    o1.z = fmaxf(acc4[3].x * zi + b1[ch + 6], 0.f);
    o1.w = fmaxf(acc4[3].y * zi + b1[ch + 7], 0.f);
    float* hd = &g_h[(long)n * C1];
    *(float4*)&hd[ch]     = o0;
    *(float4*)&hd[ch + 4] = o1;
}

// ---------- layer-2 aggregation (two-pass, fp16 gather) + log_softmax -------
__global__ __launch_bounds__(256) void agg2_kernel(const float* __restrict__ b2,
                                                   float* __restrict__ out) {
    int n = (blockIdx.x * blockDim.x + threadIdx.x) >> 5;
    int lane = threadIdx.x & 31;
    if (n >= N_NODES) return;
    const int start = g_rowstart[n];
    const int end   = g_rowstart[n + 1];
    const float adn = g_ad2[n];

    float m = -INFINITY;
    for (int i = start + lane; i < end; i += 32)
        m = fmaxf(m, leaky(g_as2[g_csrc[i]] + adn));
#pragma unroll
    for (int o = 16; o > 0; o >>= 1)
        m = fmaxf(m, __shfl_xor_sync(0xffffffffu, m, o));

    // lane < 10 owns channels 4*lane..4*lane+3 (fp16 gather: 8 bytes)
    float4 a = make_float4(0.f, 0.f, 0.f, 0.f);
    float z = 0.f;
    for (int i = start; i < end; i++) {
        int s = g_csrc[i];
        float p = __expf(leaky(g_as2[s] + adn) - m);
        z += p;
        if (lane < 10) {
            float2 raw = *(const float2*)&g_xp2h[(long)s * OUT_CH + 4 * lane];
            const __half2* hp = reinterpret_cast<const __half2*>(&raw);
            float2 f0 = __half22float2(hp[0]);
            float2 f1 = __half22float2(hp[1]);
            a.x += p * f0.x; a.y += p * f0.y; a.z += p * f1.x; a.w += p * f1.y;
        }
    }
    float zi = 1.0f / (z + 1e-16f);

    float x0 = -INFINITY, x1 = -INFINITY, x2 = -INFINITY, x3 = -INFINITY;
    if (lane < 10) {
        int ch = 4 * lane;
        x0 = a.x * zi + b2[ch + 0];
        x1 = a.y * zi + b2[ch + 1];
        x2 = a.z * zi + b2[ch + 2];
        x3 = a.w * zi + b2[ch + 3];
    }
    float mx = fmaxf(fmaxf(x0, x1), fmaxf(x2, x3));
#pragma unroll
    for (int o = 16; o > 0; o >>= 1) mx = fmaxf(mx, __shfl_xor_sync(0xffffffffu, mx, o));
    float se = 0.f;
    if (lane < 10)
        se = __expf(x0 - mx) + __expf(x1 - mx) + __expf(x2 - mx) + __expf(x3 - mx);
#pragma unroll
    for (int o = 16; o > 0; o >>= 1) se += __shfl_xor_sync(0xffffffffu, se, o);
    float lse = mx + logf(se);
    if (lane < 10) {
        float4 o4 = make_float4(x0 - lse, x1 - lse, x2 - lse, x3 - lse);
        *(float4*)&out[(long)n * OUT_CH + 4 * lane] = o4;
    }
}

// ---------------- launch ----------------------------------------------------
extern "C" void kernel_launch(void* const* d_in, const int* in_sizes, int n_in,
                              void* d_out, int out_size) {
    const float* x        = (const float*)d_in[0];
    const int*   ei       = (const int*)d_in[1];
    const float* W1       = (const float*)d_in[2];
    const float* att_src1 = (const float*)d_in[3];
    const float* att_dst1 = (const float*)d_in[4];
    const float* b1       = (const float*)d_in[5];
    const float* W2       = (const float*)d_in[6];
    const float* att_src2 = (const float*)d_in[7];
    const float* att_dst2 = (const float*)d_in[8];
    const float* b2       = (const float*)d_in[9];
    float*       out      = (float*)d_out;

    float* h = nullptr; float* xp2 = nullptr;
    cudaGetSymbolAddress((void**)&h,   g_h);
    cudaGetSymbolAddress((void**)&xp2, g_xp2);

    // CSR build (shared by both layers)
    zero_kernel<<<(N_NODES + 255) / 256, 256>>>();
    hist_kernel<<<(ET + 255) / 256, 256>>>(ei);
    scan_kernel<<<1, 1024>>>();
    scatter_kernel<<<(ET + 255) / 256, 256>>>(ei);

    // layer 1 (attn1 fused into GEMM1 epilogue; fp16-only xp1)
    {
        dim3 grid(C1 / 128, (N_NODES + 127) / 128);
        sgemm1_tc_kernel<<<grid, 256>>>(x, W1, att_src1, att_dst1, N_NODES);
    }
    agg1_kernel<<<(N_NODES * 32 + 255) / 256, 256>>>(b1);

    // layer 2 (attn2 fused into GEMM2 epilogue; fp16 mirror for agg2)
    sgemm2_tc_kernel<<<(N_NODES + 127) / 128, 256>>>(h, W2, xp2, att_src2, att_dst2, N_NODES);
    agg2_kernel<<<(N_NODES * 32 + 255) / 256, 256>>>(b2, out);
}

// round 14
// speedup vs baseline: 1.0668x; 1.0149x over previous
#include <cuda_runtime.h>
#include <cuda_fp16.h>
#include <math.h>

#define N_NODES 100000
#define E_EDGES 800000
#define ET (E_EDGES + N_NODES)   // edges + self loops = 900000
#define IN_CH 128
#define HID 32
#define HEADS 8
#define C1 (HEADS * HID)          // 256
#define OUT_CH 40
#define NEG_SLOPE 0.2f

// ---------------- scratch (device globals; no allocation allowed) ----------
__device__ __half g_xp1h[N_NODES * C1];     // fp16 xp1
__device__ __half g_hh[N_NODES * C1];       // fp16 h (layer-1 output)
__device__ __half g_xp2h[N_NODES * OUT_CH]; // fp16 xp2
__device__ float  g_as1[N_NODES * HEADS];
__device__ float  g_ad1[N_NODES * HEADS];
__device__ float  g_as2[N_NODES];
__device__ float  g_ad2[N_NODES];

__device__ int g_deg[N_NODES];
__device__ int g_rowstart[N_NODES + 1];
__device__ int g_cursor[N_NODES];
__device__ int g_csrc[ET];

__device__ __forceinline__ float leaky(float x) {
    return x > 0.0f ? x : NEG_SLOPE * x;
}

// ================= CSR build ================================================
__global__ void zero_kernel() {
    int i = blockIdx.x * blockDim.x + threadIdx.x;
    if (i < N_NODES) g_deg[i] = 0;
}

__global__ void hist_kernel(const int* __restrict__ ei) {
    int e = blockIdx.x * blockDim.x + threadIdx.x;
    if (e >= ET) return;
    int dst = (e < E_EDGES) ? ei[E_EDGES + e] : e - E_EDGES;
    atomicAdd(&g_deg[dst], 1);
}

__global__ void scan_kernel() {
    __shared__ int sums[1024];
    const int t = threadIdx.x;
    const int CH = (N_NODES + 1023) / 1024;
    int lo = t * CH;
    int hi = lo + CH; if (hi > N_NODES) hi = N_NODES;
    int s = 0;
    for (int i = lo; i < hi; i++) s += g_deg[i];
    sums[t] = s;
    __syncthreads();
    for (int o = 1; o < 1024; o <<= 1) {
        int u = (t >= o) ? sums[t - o] : 0;
        __syncthreads();
        sums[t] += u;
        __syncthreads();
    }
    int run = sums[t] - s;
    for (int i = lo; i < hi; i++) {
        g_rowstart[i] = run;
        g_cursor[i]   = run;
        run += g_deg[i];
    }
    if (t == 0) g_rowstart[N_NODES] = ET;
}

__global__ void scatter_kernel(const int* __restrict__ ei) {
    int e = blockIdx.x * blockDim.x + threadIdx.x;
    if (e >= ET) return;
    int src, dst;
    if (e < E_EDGES) { src = ei[e]; dst = ei[E_EDGES + e]; }
    else             { src = dst = e - E_EDGES; }
    int pos = atomicAdd(&g_cursor[dst], 1);
    g_csrc[pos] = src;
}

// ================= tf32 helpers =============================================
__device__ __forceinline__ unsigned tf32_of(float x) {
    unsigned r;
    asm("cvt.rna.tf32.f32 %0, %1;" : "=r"(r) : "f"(x));
    return r;
}
__device__ __forceinline__ void tf32_split(float x, unsigned& hi, unsigned& lo) {
    hi = tf32_of(x);
    float lo_f = x - __uint_as_float(hi);
    lo = tf32_of(lo_f);
}
__device__ __forceinline__ void tf32_split_f(float x, float& hi, float& lo) {
    unsigned h, l;
    tf32_split(x, h, l);
    hi = __uint_as_float(h);
    lo = __uint_as_float(l);
}
__device__ __forceinline__ void mma_tf32(float* d, const unsigned* a, const unsigned* b) {
    asm volatile(
        "mma.sync.aligned.m16n8k8.row.col.f32.tf32.tf32.f32 "
        "{%0,%1,%2,%3}, {%4,%5,%6,%7}, {%8,%9}, {%0,%1,%2,%3};"
        : "+f"(d[0]), "+f"(d[1]), "+f"(d[2]), "+f"(d[3])
        : "r"(a[0]), "r"(a[1]), "r"(a[2]), "r"(a[3]), "r"(b[0]), "r"(b[1]));
}
__device__ __forceinline__ float quad_reduce(float v) {
    v += __shfl_xor_sync(0xffffffffu, v, 1);
    v += __shfl_xor_sync(0xffffffffu, v, 2);
    return v;
}

#define PAD 136

// ============ GEMM1 (tc tf32x3) + fused attn1 dots, fp16-only output ========
__global__ __launch_bounds__(256) void sgemm1_tc_kernel(const float* __restrict__ A,
                                                        const float* __restrict__ B,
                                                        const float* __restrict__ att_src,
                                                        const float* __restrict__ att_dst,
                                                        int M) {
    __shared__ __align__(16) float AsH[2][8][PAD];
    __shared__ __align__(16) float AsL[2][8][PAD];
    __shared__ __align__(16) float BsH[2][8][PAD];
    __shared__ __align__(16) float BsL[2][8][PAD];

    const int tid  = threadIdx.x;
    const int wid  = tid >> 5;
    const int lane = tid & 31;
    const int warpM = wid & 3;
    const int warpN = wid >> 2;
    const int rowBase = blockIdx.y * 128;
    const int colBase = blockIdx.x * 128;

    const int r = lane >> 2;
    const int c = lane & 3;

    float acc[2][8][4];
#pragma unroll
    for (int i = 0; i < 2; i++)
#pragma unroll
        for (int j = 0; j < 8; j++)
#pragma unroll
            for (int q = 0; q < 4; q++) acc[i][j][q] = 0.0f;

    const int ar  = tid >> 1;
    const int akq = (tid & 1) * 4;
    const int bk  = tid >> 5;
    const int bnq = (tid & 31) * 4;
    const int gr  = rowBase + ar;

    float4 av, bv;

    av = make_float4(0.f, 0.f, 0.f, 0.f);
    if (gr < M) av = *(const float4*)&A[(long)gr * IN_CH + akq];
    bv = *(const float4*)&B[(long)bk * C1 + colBase + bnq];
    {
        float ah_, al_;
        tf32_split_f(av.x, ah_, al_); AsH[0][akq + 0][ar] = ah_; AsL[0][akq + 0][ar] = al_;
        tf32_split_f(av.y, ah_, al_); AsH[0][akq + 1][ar] = ah_; AsL[0][akq + 1][ar] = al_;
        tf32_split_f(av.z, ah_, al_); AsH[0][akq + 2][ar] = ah_; AsL[0][akq + 2][ar] = al_;
        tf32_split_f(av.w, ah_, al_); AsH[0][akq + 3][ar] = ah_; AsL[0][akq + 3][ar] = al_;
        float4 hv, lv;
        tf32_split_f(bv.x, hv.x, lv.x);
        tf32_split_f(bv.y, hv.y, lv.y);
        tf32_split_f(bv.z, hv.z, lv.z);
        tf32_split_f(bv.w, hv.w, lv.w);
        *(float4*)&BsH[0][bk][bnq] = hv;
        *(float4*)&BsL[0][bk][bnq] = lv;
    }
    __syncthreads();

    int p = 0;
#pragma unroll
    for (int s = 0; s < 16; s++) {
        if (s < 15) {
            int k0 = (s + 1) * 8;
            av = make_float4(0.f, 0.f, 0.f, 0.f);
            if (gr < M) av = *(const float4*)&A[(long)gr * IN_CH + k0 + akq];
            bv = *(const float4*)&B[(long)(k0 + bk) * C1 + colBase + bnq];
        }
        {
            unsigned ah[2][4], al[2][4];
#pragma unroll
            for (int im = 0; im < 2; im++) {
                int mb = warpM * 32 + im * 16;
                ah[im][0] = __float_as_uint(AsH[p][c][mb + r]);
                ah[im][1] = __float_as_uint(AsH[p][c][mb + 8 + r]);
                ah[im][2] = __float_as_uint(AsH[p][4 + c][mb + r]);
                ah[im][3] = __float_as_uint(AsH[p][4 + c][mb + 8 + r]);
                al[im][0] = __float_as_uint(AsL[p][c][mb + r]);
                al[im][1] = __float_as_uint(AsL[p][c][mb + 8 + r]);
                al[im][2] = __float_as_uint(AsL[p][4 + c][mb + r]);
                al[im][3] = __float_as_uint(AsL[p][4 + c][mb + 8 + r]);
            }
            unsigned bh[8][2], bl[8][2];
#pragma unroll
            for (int in = 0; in < 8; in++) {
                int nb = warpN * 64 + in * 8 + r;
                bh[in][0] = __float_as_uint(BsH[p][c][nb]);
                bh[in][1] = __float_as_uint(BsH[p][4 + c][nb]);
                bl[in][0] = __float_as_uint(BsL[p][c][nb]);
                bl[in][1] = __float_as_uint(BsL[p][4 + c][nb]);
            }
#pragma unroll
            for (int im = 0; im < 2; im++)
#pragma unroll
                for (int in = 0; in < 8; in++) {
                    mma_tf32(acc[im][in], al[im], bh[in]);
                    mma_tf32(acc[im][in], ah[im], bl[in]);
                    mma_tf32(acc[im][in], ah[im], bh[in]);
                }
        }
        if (s < 15) {
            p ^= 1;
            float ah_, al_;
            tf32_split_f(av.x, ah_, al_); AsH[p][akq + 0][ar] = ah_; AsL[p][akq + 0][ar] = al_;
            tf32_split_f(av.y, ah_, al_); AsH[p][akq + 1][ar] = ah_; AsL[p][akq + 1][ar] = al_;
            tf32_split_f(av.z, ah_, al_); AsH[p][akq + 2][ar] = ah_; AsL[p][akq + 2][ar] = al_;
            tf32_split_f(av.w, ah_, al_); AsH[p][akq + 3][ar] = ah_; AsL[p][akq + 3][ar] = al_;
            float4 hv, lv;
            tf32_split_f(bv.x, hv.x, lv.x);
            tf32_split_f(bv.y, hv.y, lv.y);
            tf32_split_f(bv.z, hv.z, lv.z);
            tf32_split_f(bv.w, hv.w, lv.w);
            *(float4*)&BsH[p][bk][bnq] = hv;
            *(float4*)&BsL[p][bk][bnq] = lv;
            __syncthreads();
        }
    }

    // epilogue: fp16 mirror + fused attn dots (exclusive (row,head) owner)
#pragma unroll
    for (int im = 0; im < 2; im++) {
        int row0 = rowBase + warpM * 32 + im * 16 + r;
        int row1 = row0 + 8;
        float s0[2] = {0.f, 0.f}, d0[2] = {0.f, 0.f};
        float s1[2] = {0.f, 0.f}, d1[2] = {0.f, 0.f};
#pragma unroll
        for (int in = 0; in < 8; in++) {
            int col = colBase + warpN * 64 + in * 8 + 2 * c;
            float w0 = att_src[col], w1 = att_src[col + 1];
            float v0 = att_dst[col], v1 = att_dst[col + 1];
            int hp = in >> 2;
            s0[hp] += acc[im][in][0] * w0 + acc[im][in][1] * w1;
            d0[hp] += acc[im][in][0] * v0 + acc[im][in][1] * v1;
            s1[hp] += acc[im][in][2] * w0 + acc[im][in][3] * w1;
            d1[hp] += acc[im][in][2] * v0 + acc[im][in][3] * v1;
            if (row0 < M)
                *(__half2*)&g_xp1h[(long)row0 * C1 + col] =
                    __float22half2_rn(make_float2(acc[im][in][0], acc[im][in][1]));
            if (row1 < M)
                *(__half2*)&g_xp1h[(long)row1 * C1 + col] =
                    __float22half2_rn(make_float2(acc[im][in][2], acc[im][in][3]));
        }
#pragma unroll
        for (int hp = 0; hp < 2; hp++) {
            s0[hp] = quad_reduce(s0[hp]); d0[hp] = quad_reduce(d0[hp]);
            s1[hp] = quad_reduce(s1[hp]); d1[hp] = quad_reduce(d1[hp]);
        }
        if (c == 0) {
            int hbase = (colBase >> 5) + warpN * 2;
#pragma unroll
            for (int hp = 0; hp < 2; hp++) {
                if (row0 < M) {
                    g_as1[row0 * 8 + hbase + hp] = s0[hp];
                    g_ad1[row0 * 8 + hbase + hp] = d0[hp];
                }
                if (row1 < M) {
                    g_as1[row1 * 8 + hbase + hp] = s1[hp];
                    g_ad1[row1 * 8 + hbase + hp] = d1[hp];
                }
            }
        }
    }
}

// ============ GEMM2 (tc tf32x3, fp16 A) + fused attn2 dots ==================
__global__ __launch_bounds__(256) void sgemm2_tc_kernel(const float* __restrict__ B,
                                                        const float* __restrict__ att_src,
                                                        const float* __restrict__ att_dst,
                                                        int M) {
    __shared__ __align__(16) float As[2][16][PAD];
    __shared__ float BsH[2][16][40];
    __shared__ float BsL[2][16][40];

    const int tid  = threadIdx.x;
    const int wid  = tid >> 5;
    const int lane = tid & 31;
    const int rowBase = blockIdx.x * 128;
    const int r = lane >> 2;
    const int c = lane & 3;

    float acc[5][4];
#pragma unroll
    for (int j = 0; j < 5; j++)
#pragma unroll
        for (int q = 0; q < 4; q++) acc[j][q] = 0.0f;

    // A loader: one uint4 (8 fp16) per thread per stage
    const int ar  = tid >> 1;            // 0..127
    const int akq = (tid & 1) * 8;       // 0 or 8
    const int gr  = rowBase + ar;

    uint4  araw;
    float  bsc[3];

    araw = make_uint4(0, 0, 0, 0);
    if (gr < M) araw = *(const uint4*)&g_hh[(long)gr * C1 + akq];
#pragma unroll
    for (int t = 0; t < 3; t++) {
        int idx = tid + t * 256;
        bsc[t] = (idx < 16 * 40) ? B[(long)(idx / 40) * OUT_CH + idx % 40] : 0.f;
    }
    {
        const __half2* hp = reinterpret_cast<const __half2*>(&araw);
#pragma unroll
        for (int q = 0; q < 4; q++) {
            float2 f = __half22float2(hp[q]);
            As[0][akq + 2 * q + 0][ar] = f.x;
            As[0][akq + 2 * q + 1][ar] = f.y;
        }
    }
#pragma unroll
    for (int t = 0; t < 3; t++) {
        int idx = tid + t * 256;
        if (idx < 16 * 40) {
            float h_, l_;
            tf32_split_f(bsc[t], h_, l_);
            BsH[0][idx / 40][idx % 40] = h_;
            BsL[0][idx / 40][idx % 40] = l_;
        }
    }
    __syncthreads();

    int p = 0;
#pragma unroll
    for (int s = 0; s < 16; s++) {
        if (s < 15) {
            int k0 = (s + 1) * 16;
            araw = make_uint4(0, 0, 0, 0);
            if (gr < M) araw = *(const uint4*)&g_hh[(long)gr * C1 + k0 + akq];
#pragma unroll
            for (int t = 0; t < 3; t++) {
                int idx = tid + t * 256;
                bsc[t] = (idx < 16 * 40) ? B[(long)(k0 + idx / 40) * OUT_CH + idx % 40] : 0.f;
            }
        }
#pragma unroll
        for (int kk = 0; kk < 16; kk += 8) {
            unsigned ah[4], al[4];
            {
                int mb = wid * 16;
                tf32_split(As[p][kk + c][mb + r],         ah[0], al[0]);
                tf32_split(As[p][kk + c][mb + 8 + r],     ah[1], al[1]);
                tf32_split(As[p][kk + 4 + c][mb + r],     ah[2], al[2]);
                tf32_split(As[p][kk + 4 + c][mb + 8 + r], ah[3], al[3]);
            }
#pragma unroll
            for (int in = 0; in < 5; in++) {
                int nb = in * 8 + r;
                unsigned bh[2], bl[2];
                bh[0] = __float_as_uint(BsH[p][kk + c][nb]);
                bh[1] = __float_as_uint(BsH[p][kk + 4 + c][nb]);
                bl[0] = __float_as_uint(BsL[p][kk + c][nb]);
                bl[1] = __float_as_uint(BsL[p][kk + 4 + c][nb]);
                mma_tf32(acc[in], al, bh);
                mma_tf32(acc[in], ah, bl);
                mma_tf32(acc[in], ah, bh);
            }
        }
        if (s < 15) {
            p ^= 1;
            {
                const __half2* hp = reinterpret_cast<const __half2*>(&araw);
#pragma unroll
                for (int q = 0; q < 4; q++) {
                    float2 f = __half22float2(hp[q]);
                    As[p][akq + 2 * q + 0][ar] = f.x;
                    As[p][akq + 2 * q + 1][ar] = f.y;
                }
            }
#pragma unroll
            for (int t = 0; t < 3; t++) {
                int idx = tid + t * 256;
                if (idx < 16 * 40) {
                    float h_, l_;
                    tf32_split_f(bsc[t], h_, l_);
                    BsH[p][idx / 40][idx % 40] = h_;
                    BsL[p][idx / 40][idx % 40] = l_;
                }
            }
            __syncthreads();
        }
    }

    // epilogue: fp16 mirror + fused attn2 dots (no fp32 C store — dead)
    {
        int row0 = rowBase + wid * 16 + r;
        int row1 = row0 + 8;
        float s0 = 0.f, d0 = 0.f, s1 = 0.f, d1 = 0.f;
#pragma unroll
        for (int in = 0; in < 5; in++) {
            int col = in * 8 + 2 * c;
            float w0 = att_src[col], w1 = att_src[col + 1];
            float v0 = att_dst[col], v1 = att_dst[col + 1];
            s0 += acc[in][0] * w0 + acc[in][1] * w1;
            d0 += acc[in][0] * v0 + acc[in][1] * v1;
            s1 += acc[in][2] * w0 + acc[in][3] * w1;
            d1 += acc[in][2] * v0 + acc[in][3] * v1;
            if (row0 < M)
                *(__half2*)&g_xp2h[(long)row0 * OUT_CH + col] =
                    __float22half2_rn(make_float2(acc[in][0], acc[in][1]));
            if (row1 < M)
                *(__half2*)&g_xp2h[(long)row1 * OUT_CH + col] =
                    __float22half2_rn(make_float2(acc[in][2], acc[in][3]));
        }
        s0 = quad_reduce(s0); d0 = quad_reduce(d0);
        s1 = quad_reduce(s1); d1 = quad_reduce(d1);
        if (c == 0) {
            if (row0 < M) { g_as2[row0] = s0; g_ad2[row0] = d0; }
            if (row1 < M) { g_as2[row1] = s1; g_ad2[row1] = d1; }
        }
    }
}

// ------- layer-1 aggregation: two-pass, unroll-2 fp16 gather, fp16 out ------
__global__ __launch_bounds__(256) void agg1_kernel(const float* __restrict__ b1) {
    int n = (blockIdx.x * blockDim.x + threadIdx.x) >> 5;
    int lane = threadIdx.x & 31;
    if (n >= N_NODES) return;
    const int start = g_rowstart[n];
    const int end   = g_rowstart[n + 1];

    const int h   = lane & 7;
    const int grp = lane >> 3;
    const float adv = g_ad1[n * 8 + h];

    // pass 1: per-head max
    float m = -INFINITY;
    for (int i = start + grp; i < end; i += 4) {
        int s = g_csrc[i];
        m = fmaxf(m, leaky(g_as1[s * 8 + h] + adv));
    }
    m = fmaxf(m, __shfl_xor_sync(0xffffffffu, m, 8));
    m = fmaxf(m, __shfl_xor_sync(0xffffffffu, m, 16));

    // pass 2: exp + fp16 float4 gather, 2 edges per iteration (MLP=2)
    float2 acc4[4];
#pragma unroll
    for (int q = 0; q < 4; q++) acc4[q] = make_float2(0.f, 0.f);
    float z = 0.f;
    const int hsel = lane >> 2;
    int i = start;
    for (; i + 1 < end; i += 2) {
        int sA = g_csrc[i];
        int sB = g_csrc[i + 1];
        float pA = 0.f, pB = 0.f;
        if (lane < 8) {
            pA = __expf(leaky(g_as1[sA * 8 + lane] + adv) - m);
            pB = __expf(leaky(g_as1[sB * 8 + lane] + adv) - m);
            z += pA + pB;
        }
        float4 rawA = *(const float4*)&g_xp1h[(long)sA * C1 + 8 * lane];
        float4 rawB = *(const float4*)&g_xp1h[(long)sB * C1 + 8 * lane];
        float phA = __shfl_sync(0xffffffffu, pA, hsel);
        float phB = __shfl_sync(0xffffffffu, pB, hsel);
        const __half2* hpA = reinterpret_cast<const __half2*>(&rawA);
        const __half2* hpB = reinterpret_cast<const __half2*>(&rawB);
#pragma unroll
        for (int q = 0; q < 4; q++) {
            float2 fA = __half22float2(hpA[q]);
            float2 fB = __half22float2(hpB[q]);
            acc4[q].x += phA * fA.x + phB * fB.x;
            acc4[q].y += phA * fA.y + phB * fB.y;
        }
    }
    if (i < end) {
        int s = g_csrc[i];
        float p = 0.f;
        if (lane < 8) {
            p = __expf(leaky(g_as1[s * 8 + lane] + adv) - m);
            z += p;
        }
        float4 raw = *(const float4*)&g_xp1h[(long)s * C1 + 8 * lane];
        float ph = __shfl_sync(0xffffffffu, p, hsel);
        const __half2* hp = reinterpret_cast<const __half2*>(&raw);
#pragma unroll
        for (int q = 0; q < 4; q++) {
            float2 f = __half22float2(hp[q]);
            acc4[q].x += ph * f.x;
            acc4[q].y += ph * f.y;
        }
    }

    // finalize: divide, bias, relu -> fp16 g_hh
    float zh = __shfl_sync(0xffffffffu, z, hsel);
    float zi = 1.0f / (zh + 1e-16f);
    int ch = 8 * lane;
    float o[8];
    o[0] = fmaxf(acc4[0].x * zi + b1[ch + 0], 0.f);
    o[1] = fmaxf(acc4[0].y * zi + b1[ch + 1], 0.f);
    o[2] = fmaxf(acc4[1].x * zi + b1[ch + 2], 0.f);
    o[3] = fmaxf(acc4[1].y * zi + b1[ch + 3], 0.f);
    o[4] = fmaxf(acc4[2].x * zi + b1[ch + 4], 0.f);
    o[5] = fmaxf(acc4[2].y * zi + b1[ch + 5], 0.f);
    o[6] = fmaxf(acc4[3].x * zi + b1[ch + 6], 0.f);
    o[7] = fmaxf(acc4[3].y * zi + b1[ch + 7], 0.f);
    __half2 q0 = __floats2half2_rn(o[0], o[1]);
    __half2 q1 = __floats2half2_rn(o[2], o[3]);
    __half2 q2 = __floats2half2_rn(o[4], o[5]);
    __half2 q3 = __floats2half2_rn(o[6], o[7]);
    uint4 pack;
    pack.x = *(unsigned*)&q0; pack.y = *(unsigned*)&q1;
    pack.z = *(unsigned*)&q2; pack.w = *(unsigned*)&q3;
    *(uint4*)&g_hh[(long)n * C1 + ch] = pack;
}

// ---------- layer-2 aggregation (two-pass, unroll-2) + log_softmax ----------
__global__ __launch_bounds__(256) void agg2_kernel(const float* __restrict__ b2,
                                                   float* __restrict__ out) {
    int n = (blockIdx.x * blockDim.x + threadIdx.x) >> 5;
    int lane = threadIdx.x & 31;
    if (n >= N_NODES) return;
    const int start = g_rowstart[n];
    const int end   = g_rowstart[n + 1];
    const float adn = g_ad2[n];

    float m = -INFINITY;
    for (int i = start + lane; i < end; i += 32)
        m = fmaxf(m, leaky(g_as2[g_csrc[i]] + adn));
#pragma unroll
    for (int o = 16; o > 0; o >>= 1)
        m = fmaxf(m, __shfl_xor_sync(0xffffffffu, m, o));

    // lane < 10 owns channels 4*lane..4*lane+3 (fp16 gather), 2 edges / iter
    float4 a = make_float4(0.f, 0.f, 0.f, 0.f);
    float z = 0.f;
    int i = start;
    for (; i + 1 < end; i += 2) {
        int sA = g_csrc[i];
        int sB = g_csrc[i + 1];
        float pA = __expf(leaky(g_as2[sA] + adn) - m);
        float pB = __expf(leaky(g_as2[sB] + adn) - m);
        z += pA + pB;
        if (lane < 10) {
            float2 rawA = *(const float2*)&g_xp2h[(long)sA * OUT_CH + 4 * lane];
            float2 rawB = *(const float2*)&g_xp2h[(long)sB * OUT_CH + 4 * lane];
            const __half2* hpA = reinterpret_cast<const __half2*>(&rawA);
            const __half2* hpB = reinterpret_cast<const __half2*>(&rawB);
            float2 fA0 = __half22float2(hpA[0]), fA1 = __half22float2(hpA[1]);
            float2 fB0 = __half22float2(hpB[0]), fB1 = __half22float2(hpB[1]);
            a.x += pA * fA0.x + pB * fB0.x;
            a.y += pA * fA0.y + pB * fB0.y;
            a.z += pA * fA1.x + pB * fB1.x;
            a.w += pA * fA1.y + pB * fB1.y;
        }
    }
    if (i < end) {
        int s = g_csrc[i];
        float p = __expf(leaky(g_as2[s] + adn) - m);
        z += p;
        if (lane < 10) {
            float2 raw = *(const float2*)&g_xp2h[(long)s * OUT_CH + 4 * lane];
            const __half2* hp = reinterpret_cast<const __half2*>(&raw);
            float2 f0 = __half22float2(hp[0]);
            float2 f1 = __half22float2(hp[1]);
            a.x += p * f0.x; a.y += p * f0.y; a.z += p * f1.x; a.w += p * f1.y;
        }
    }
    float zi = 1.0f / (z + 1e-16f);

    float x0 = -INFINITY, x1 = -INFINITY, x2 = -INFINITY, x3 = -INFINITY;
    if (lane < 10) {
        int ch = 4 * lane;
        x0 = a.x * zi + b2[ch + 0];
        x1 = a.y * zi + b2[ch + 1];
        x2 = a.z * zi + b2[ch + 2];
        x3 = a.w * zi + b2[ch + 3];
    }
    float mx = fmaxf(fmaxf(x0, x1), fmaxf(x2, x3));
#pragma unroll
    for (int o = 16; o > 0; o >>= 1) mx = fmaxf(mx, __shfl_xor_sync(0xffffffffu, mx, o));
    float se = 0.f;
    if (lane < 10)
        se = __expf(x0 - mx) + __expf(x1 - mx) + __expf(x2 - mx) + __expf(x3 - mx);
#pragma unroll
    for (int o = 16; o > 0; o >>= 1) se += __shfl_xor_sync(0xffffffffu, se, o);
    float lse = mx + logf(se);
    if (lane < 10) {
        float4 o4 = make_float4(x0 - lse, x1 - lse, x2 - lse, x3 - lse);
        *(float4*)&out[(long)n * OUT_CH + 4 * lane] = o4;
    }
}

// ---------------- launch ----------------------------------------------------
extern "C" void kernel_launch(void* const* d_in, const int* in_sizes, int n_in,
                              void* d_out, int out_size) {
    const float* x        = (const float*)d_in[0];
    const int*   ei       = (const int*)d_in[1];
    const float* W1       = (const float*)d_in[2];
    const float* att_src1 = (const float*)d_in[3];
    const float* att_dst1 = (const float*)d_in[4];
    const float* b1       = (const float*)d_in[5];
    const float* W2       = (const float*)d_in[6];
    const float* att_src2 = (const float*)d_in[7];
    const float* att_dst2 = (const float*)d_in[8];
    const float* b2       = (const float*)d_in[9];
    float*       out      = (float*)d_out;

    // CSR build (shared by both layers)
    zero_kernel<<<(N_NODES + 255) / 256, 256>>>();
    hist_kernel<<<(ET + 255) / 256, 256>>>(ei);
    scan_kernel<<<1, 1024>>>();
    scatter_kernel<<<(ET + 255) / 256, 256>>>(ei);

    // layer 1
    {
        dim3 grid(C1 / 128, (N_NODES + 127) / 128);
        sgemm1_tc_kernel<<<grid, 256>>>(x, W1, att_src1, att_dst1, N_NODES);
    }
    agg1_kernel<<<(N_NODES * 32 + 255) / 256, 256>>>(b1);

    // layer 2
    sgemm2_tc_kernel<<<(N_NODES + 127) / 128, 256>>>(W2, att_src2, att_dst2, N_NODES);
    agg2_kernel<<<(N_NODES * 32 + 255) / 256, 256>>>(b2, out);
}

// round 15
// speedup vs baseline: 1.0819x; 1.0141x over previous
#include <cuda_runtime.h>
#include <cuda_fp16.h>
#include <math.h>

#define N_NODES 100000
#define E_EDGES 800000
#define ET (E_EDGES + N_NODES)   // edges + self loops = 900000
#define IN_CH 128
#define HID 32
#define HEADS 8
#define C1 (HEADS * HID)          // 256
#define OUT_CH 40
#define NEG_SLOPE 0.2f

// ---------------- scratch (device globals; no allocation allowed) ----------
__device__ __half g_xp1h[N_NODES * C1];     // fp16 xp1
__device__ __half g_hh[N_NODES * C1];       // fp16 h (layer-1 output)
__device__ __half g_xp2h[N_NODES * OUT_CH]; // fp16 xp2
__device__ float  g_as1[N_NODES * HEADS];
__device__ float  g_ad1[N_NODES * HEADS];
__device__ float  g_as2[N_NODES];
__device__ float  g_ad2[N_NODES];

__device__ int g_deg[N_NODES];
__device__ int g_rowstart[N_NODES + 1];
__device__ int g_cursor[N_NODES];
__device__ int g_csrc[ET];

__device__ __forceinline__ float leaky(float x) {
    return x > 0.0f ? x : NEG_SLOPE * x;
}

// ---- side-stream handles: created once at load time (pre-baseline), ----
// ---- kernel_launch does identical work on every call ---------------------
struct SideStream {
    cudaStream_t s;
    cudaEvent_t  fork, join;
    SideStream() {
        cudaStreamCreateWithFlags(&s, cudaStreamNonBlocking);
        cudaEventCreateWithFlags(&fork, cudaEventDisableTiming);
        cudaEventCreateWithFlags(&join, cudaEventDisableTiming);
    }
};
static SideStream g_ss;

// ================= CSR build ================================================
__global__ void zero_kernel() {
    int i = blockIdx.x * blockDim.x + threadIdx.x;
    if (i < N_NODES) g_deg[i] = 0;
}

__global__ void hist_kernel(const int* __restrict__ ei) {
    int e = blockIdx.x * blockDim.x + threadIdx.x;
    if (e >= ET) return;
    int dst = (e < E_EDGES) ? ei[E_EDGES + e] : e - E_EDGES;
    atomicAdd(&g_deg[dst], 1);
}

__global__ void scan_kernel() {
    __shared__ int sums[1024];
    const int t = threadIdx.x;
    const int CH = (N_NODES + 1023) / 1024;
    int lo = t * CH;
    int hi = lo + CH; if (hi > N_NODES) hi = N_NODES;
    int s = 0;
    for (int i = lo; i < hi; i++) s += g_deg[i];
    sums[t] = s;
    __syncthreads();
    for (int o = 1; o < 1024; o <<= 1) {
        int u = (t >= o) ? sums[t - o] : 0;
        __syncthreads();
        sums[t] += u;
        __syncthreads();
    }
    int run = sums[t] - s;
    for (int i = lo; i < hi; i++) {
        g_rowstart[i] = run;
        g_cursor[i]   = run;
        run += g_deg[i];
    }
    if (t == 0) g_rowstart[N_NODES] = ET;
}

__global__ void scatter_kernel(const int* __restrict__ ei) {
    int e = blockIdx.x * blockDim.x + threadIdx.x;
    if (e >= ET) return;
    int src, dst;
    if (e < E_EDGES) { src = ei[e]; dst = ei[E_EDGES + e]; }
    else             { src = dst = e - E_EDGES; }
    int pos = atomicAdd(&g_cursor[dst], 1);
    g_csrc[pos] = src;
}

// ================= tf32 helpers =============================================
__device__ __forceinline__ unsigned tf32_of(float x) {
    unsigned r;
    asm("cvt.rna.tf32.f32 %0, %1;" : "=r"(r) : "f"(x));
    return r;
}
__device__ __forceinline__ void tf32_split(float x, unsigned& hi, unsigned& lo) {
    hi = tf32_of(x);
    float lo_f = x - __uint_as_float(hi);
    lo = tf32_of(lo_f);
}
__device__ __forceinline__ void tf32_split_f(float x, float& hi, float& lo) {
    unsigned h, l;
    tf32_split(x, h, l);
    hi = __uint_as_float(h);
    lo = __uint_as_float(l);
}
__device__ __forceinline__ void mma_tf32(float* d, const unsigned* a, const unsigned* b) {
    asm volatile(
        "mma.sync.aligned.m16n8k8.row.col.f32.tf32.tf32.f32 "
        "{%0,%1,%2,%3}, {%4,%5,%6,%7}, {%8,%9}, {%0,%1,%2,%3};"
        : "+f"(d[0]), "+f"(d[1]), "+f"(d[2]), "+f"(d[3])
        : "r"(a[0]), "r"(a[1]), "r"(a[2]), "r"(a[3]), "r"(b[0]), "r"(b[1]));
}
__device__ __forceinline__ float quad_reduce(float v) {
    v += __shfl_xor_sync(0xffffffffu, v, 1);
    v += __shfl_xor_sync(0xffffffffu, v, 2);
    return v;
}

#define PAD 136

// ============ GEMM1 (tc tf32x3) + fused attn1 dots, fp16-only output ========
__global__ __launch_bounds__(256) void sgemm1_tc_kernel(const float* __restrict__ A,
                                                        const float* __restrict__ B,
                                                        const float* __restrict__ att_src,
                                                        const float* __restrict__ att_dst,
                                                        int M) {
    __shared__ __align__(16) float AsH[2][8][PAD];
    __shared__ __align__(16) float AsL[2][8][PAD];
    __shared__ __align__(16) float BsH[2][8][PAD];
    __shared__ __align__(16) float BsL[2][8][PAD];

    const int tid  = threadIdx.x;
    const int wid  = tid >> 5;
    const int lane = tid & 31;
    const int warpM = wid & 3;
    const int warpN = wid >> 2;
    const int rowBase = blockIdx.y * 128;
    const int colBase = blockIdx.x * 128;

    const int r = lane >> 2;
    const int c = lane & 3;

    float acc[2][8][4];
#pragma unroll
    for (int i = 0; i < 2; i++)
#pragma unroll
        for (int j = 0; j < 8; j++)
#pragma unroll
            for (int q = 0; q < 4; q++) acc[i][j][q] = 0.0f;

    const int ar  = tid >> 1;
    const int akq = (tid & 1) * 4;
    const int bk  = tid >> 5;
    const int bnq = (tid & 31) * 4;
    const int gr  = rowBase + ar;

    float4 av, bv;

    av = make_float4(0.f, 0.f, 0.f, 0.f);
    if (gr < M) av = *(const float4*)&A[(long)gr * IN_CH + akq];
    bv = *(const float4*)&B[(long)bk * C1 + colBase + bnq];
    {
        float ah_, al_;
        tf32_split_f(av.x, ah_, al_); AsH[0][akq + 0][ar] = ah_; AsL[0][akq + 0][ar] = al_;
        tf32_split_f(av.y, ah_, al_); AsH[0][akq + 1][ar] = ah_; AsL[0][akq + 1][ar] = al_;
        tf32_split_f(av.z, ah_, al_); AsH[0][akq + 2][ar] = ah_; AsL[0][akq + 2][ar] = al_;
        tf32_split_f(av.w, ah_, al_); AsH[0][akq + 3][ar] = ah_; AsL[0][akq + 3][ar] = al_;
        float4 hv, lv;
        tf32_split_f(bv.x, hv.x, lv.x);
        tf32_split_f(bv.y, hv.y, lv.y);
        tf32_split_f(bv.z, hv.z, lv.z);
        tf32_split_f(bv.w, hv.w, lv.w);
        *(float4*)&BsH[0][bk][bnq] = hv;
        *(float4*)&BsL[0][bk][bnq] = lv;
    }
    __syncthreads();

    int p = 0;
#pragma unroll
    for (int s = 0; s < 16; s++) {
        if (s < 15) {
            int k0 = (s + 1) * 8;
            av = make_float4(0.f, 0.f, 0.f, 0.f);
            if (gr < M) av = *(const float4*)&A[(long)gr * IN_CH + k0 + akq];
            bv = *(const float4*)&B[(long)(k0 + bk) * C1 + colBase + bnq];
        }
        {
            unsigned ah[2][4], al[2][4];
#pragma unroll
            for (int im = 0; im < 2; im++) {
                int mb = warpM * 32 + im * 16;
                ah[im][0] = __float_as_uint(AsH[p][c][mb + r]);
                ah[im][1] = __float_as_uint(AsH[p][c][mb + 8 + r]);
                ah[im][2] = __float_as_uint(AsH[p][4 + c][mb + r]);
                ah[im][3] = __float_as_uint(AsH[p][4 + c][mb + 8 + r]);
                al[im][0] = __float_as_uint(AsL[p][c][mb + r]);
                al[im][1] = __float_as_uint(AsL[p][c][mb + 8 + r]);
                al[im][2] = __float_as_uint(AsL[p][4 + c][mb + r]);
                al[im][3] = __float_as_uint(AsL[p][4 + c][mb + 8 + r]);
            }
            unsigned bh[8][2], bl[8][2];
#pragma unroll
            for (int in = 0; in < 8; in++) {
                int nb = warpN * 64 + in * 8 + r;
                bh[in][0] = __float_as_uint(BsH[p][c][nb]);
                bh[in][1] = __float_as_uint(BsH[p][4 + c][nb]);
                bl[in][0] = __float_as_uint(BsL[p][c][nb]);
                bl[in][1] = __float_as_uint(BsL[p][4 + c][nb]);
            }
#pragma unroll
            for (int im = 0; im < 2; im++)
#pragma unroll
                for (int in = 0; in < 8; in++) {
                    mma_tf32(acc[im][in], al[im], bh[in]);
                    mma_tf32(acc[im][in], ah[im], bl[in]);
                    mma_tf32(acc[im][in], ah[im], bh[in]);
                }
        }
        if (s < 15) {
            p ^= 1;
            float ah_, al_;
            tf32_split_f(av.x, ah_, al_); AsH[p][akq + 0][ar] = ah_; AsL[p][akq + 0][ar] = al_;
            tf32_split_f(av.y, ah_, al_); AsH[p][akq + 1][ar] = ah_; AsL[p][akq + 1][ar] = al_;
            tf32_split_f(av.z, ah_, al_); AsH[p][akq + 2][ar] = ah_; AsL[p][akq + 2][ar] = al_;
            tf32_split_f(av.w, ah_, al_); AsH[p][akq + 3][ar] = ah_; AsL[p][akq + 3][ar] = al_;
            float4 hv, lv;
            tf32_split_f(bv.x, hv.x, lv.x);
            tf32_split_f(bv.y, hv.y, lv.y);
            tf32_split_f(bv.z, hv.z, lv.z);
            tf32_split_f(bv.w, hv.w, lv.w);
            *(float4*)&BsH[p][bk][bnq] = hv;
            *(float4*)&BsL[p][bk][bnq] = lv;
            __syncthreads();
        }
    }

    // epilogue: fp16 mirror + fused attn dots (exclusive (row,head) owner)
#pragma unroll
    for (int im = 0; im < 2; im++) {
        int row0 = rowBase + warpM * 32 + im * 16 + r;
        int row1 = row0 + 8;
        float s0[2] = {0.f, 0.f}, d0[2] = {0.f, 0.f};
        float s1[2] = {0.f, 0.f}, d1[2] = {0.f, 0.f};
#pragma unroll
        for (int in = 0; in < 8; in++) {
            int col = colBase + warpN * 64 + in * 8 + 2 * c;
            float w0 = att_src[col], w1 = att_src[col + 1];
            float v0 = att_dst[col], v1 = att_dst[col + 1];
            int hp = in >> 2;
            s0[hp] += acc[im][in][0] * w0 + acc[im][in][1] * w1;
            d0[hp] += acc[im][in][0] * v0 + acc[im][in][1] * v1;
            s1[hp] += acc[im][in][2] * w0 + acc[im][in][3] * w1;
            d1[hp] += acc[im][in][2] * v0 + acc[im][in][3] * v1;
            if (row0 < M)
                *(__half2*)&g_xp1h[(long)row0 * C1 + col] =
                    __float22half2_rn(make_float2(acc[im][in][0], acc[im][in][1]));
            if (row1 < M)
                *(__half2*)&g_xp1h[(long)row1 * C1 + col] =
                    __float22half2_rn(make_float2(acc[im][in][2], acc[im][in][3]));
        }
#pragma unroll
        for (int hp = 0; hp < 2; hp++) {
            s0[hp] = quad_reduce(s0[hp]); d0[hp] = quad_reduce(d0[hp]);
            s1[hp] = quad_reduce(s1[hp]); d1[hp] = quad_reduce(d1[hp]);
        }
        if (c == 0) {
            int hbase = (colBase >> 5) + warpN * 2;
#pragma unroll
            for (int hp = 0; hp < 2; hp++) {
                if (row0 < M) {
                    g_as1[row0 * 8 + hbase + hp] = s0[hp];
                    g_ad1[row0 * 8 + hbase + hp] = d0[hp];
                }
                if (row1 < M) {
                    g_as1[row1 * 8 + hbase + hp] = s1[hp];
                    g_ad1[row1 * 8 + hbase + hp] = d1[hp];
                }
            }
        }
    }
}

// ============ GEMM2 (tc tf32x3, fp16 A) + fused attn2 dots ==================
__global__ __launch_bounds__(256) void sgemm2_tc_kernel(const float* __restrict__ B,
                                                        const float* __restrict__ att_src,
                                                        const float* __restrict__ att_dst,
                                                        int M) {
    __shared__ __align__(16) float As[2][16][PAD];
    __shared__ float BsH[2][16][40];
    __shared__ float BsL[2][16][40];

    const int tid  = threadIdx.x;
    const int wid  = tid >> 5;
    const int lane = tid & 31;
    const int rowBase = blockIdx.x * 128;
    const int r = lane >> 2;
    const int c = lane & 3;

    float acc[5][4];
#pragma unroll
    for (int j = 0; j < 5; j++)
#pragma unroll
        for (int q = 0; q < 4; q++) acc[j][q] = 0.0f;

    const int ar  = tid >> 1;
    const int akq = (tid & 1) * 8;
    const int gr  = rowBase + ar;

    uint4  araw;
    float  bsc[3];

    araw = make_uint4(0, 0, 0, 0);
    if (gr < M) araw = *(const uint4*)&g_hh[(long)gr * C1 + akq];
#pragma unroll
    for (int t = 0; t < 3; t++) {
        int idx = tid + t * 256;
        bsc[t] = (idx < 16 * 40) ? B[(long)(idx / 40) * OUT_CH + idx % 40] : 0.f;
    }
    {
        const __half2* hp = reinterpret_cast<const __half2*>(&araw);
#pragma unroll
        for (int q = 0; q < 4; q++) {
            float2 f = __half22float2(hp[q]);
            As[0][akq + 2 * q + 0][ar] = f.x;
            As[0][akq + 2 * q + 1][ar] = f.y;
        }
    }
#pragma unroll
    for (int t = 0; t < 3; t++) {
        int idx = tid + t * 256;
        if (idx < 16 * 40) {
            float h_, l_;
            tf32_split_f(bsc[t], h_, l_);
            BsH[0][idx / 40][idx % 40] = h_;
            BsL[0][idx / 40][idx % 40] = l_;
        }
    }
    __syncthreads();

    int p = 0;
#pragma unroll
    for (int s = 0; s < 16; s++) {
        if (s < 15) {
            int k0 = (s + 1) * 16;
            araw = make_uint4(0, 0, 0, 0);
            if (gr < M) araw = *(const uint4*)&g_hh[(long)gr * C1 + k0 + akq];
#pragma unroll
            for (int t = 0; t < 3; t++) {
                int idx = tid + t * 256;
                bsc[t] = (idx < 16 * 40) ? B[(long)(k0 + idx / 40) * OUT_CH + idx % 40] : 0.f;
            }
        }
#pragma unroll
        for (int kk = 0; kk < 16; kk += 8) {
            unsigned ah[4], al[4];
            {
                int mb = wid * 16;
                tf32_split(As[p][kk + c][mb + r],         ah[0], al[0]);
                tf32_split(As[p][kk + c][mb + 8 + r],     ah[1], al[1]);
                tf32_split(As[p][kk + 4 + c][mb + r],     ah[2], al[2]);
                tf32_split(As[p][kk + 4 + c][mb + 8 + r], ah[3], al[3]);
            }
#pragma unroll
            for (int in = 0; in < 5; in++) {
                int nb = in * 8 + r;
                unsigned bh[2], bl[2];
                bh[0] = __float_as_uint(BsH[p][kk + c][nb]);
                bh[1] = __float_as_uint(BsH[p][kk + 4 + c][nb]);
                bl[0] = __float_as_uint(BsL[p][kk + c][nb]);
                bl[1] = __float_as_uint(BsL[p][kk + 4 + c][nb]);
                mma_tf32(acc[in], al, bh);
                mma_tf32(acc[in], ah, bl);
                mma_tf32(acc[in], ah, bh);
            }
        }
        if (s < 15) {
            p ^= 1;
            {
                const __half2* hp = reinterpret_cast<const __half2*>(&araw);
#pragma unroll
                for (int q = 0; q < 4; q++) {
                    float2 f = __half22float2(hp[q]);
                    As[p][akq + 2 * q + 0][ar] = f.x;
                    As[p][akq + 2 * q + 1][ar] = f.y;
                }
            }
#pragma unroll
            for (int t = 0; t < 3; t++) {
                int idx = tid + t * 256;
                if (idx < 16 * 40) {
                    float h_, l_;
                    tf32_split_f(bsc[t], h_, l_);
                    BsH[p][idx / 40][idx % 40] = h_;
                    BsL[p][idx / 40][idx % 40] = l_;
                }
            }
            __syncthreads();
        }
    }

    // epilogue: fp16 mirror + fused attn2 dots
    {
        int row0 = rowBase + wid * 16 + r;
        int row1 = row0 + 8;
        float s0 = 0.f, d0 = 0.f, s1 = 0.f, d1 = 0.f;
#pragma unroll
        for (int in = 0; in < 5; in++) {
            int col = in * 8 + 2 * c;
            float w0 = att_src[col], w1 = att_src[col + 1];
            float v0 = att_dst[col], v1 = att_dst[col + 1];
            s0 += acc[in][0] * w0 + acc[in][1] * w1;
            d0 += acc[in][0] * v0 + acc[in][1] * v1;
            s1 += acc[in][2] * w0 + acc[in][3] * w1;
            d1 += acc[in][2] * v0 + acc[in][3] * v1;
            if (row0 < M)
                *(__half2*)&g_xp2h[(long)row0 * OUT_CH + col] =
                    __float22half2_rn(make_float2(acc[in][0], acc[in][1]));
            if (row1 < M)
                *(__half2*)&g_xp2h[(long)row1 * OUT_CH + col] =
                    __float22half2_rn(make_float2(acc[in][2], acc[in][3]));
        }
        s0 = quad_reduce(s0); d0 = quad_reduce(d0);
        s1 = quad_reduce(s1); d1 = quad_reduce(d1);
        if (c == 0) {
            if (row0 < M) { g_as2[row0] = s0; g_ad2[row0] = d0; }
            if (row1 < M) { g_as2[row1] = s1; g_ad2[row1] = d1; }
        }
    }
}

// ------- layer-1 aggregation: two-pass, unroll-2 fp16 gather, fp16 out ------
__global__ __launch_bounds__(256) void agg1_kernel(const float* __restrict__ b1) {
    int n = (blockIdx.x * blockDim.x + threadIdx.x) >> 5;
    int lane = threadIdx.x & 31;
    if (n >= N_NODES) return;
    const int start = g_rowstart[n];
    const int end   = g_rowstart[n + 1];

    const int h   = lane & 7;
    const int grp = lane >> 3;
    const float adv = g_ad1[n * 8 + h];

    // pass 1: per-head max
    float m = -INFINITY;
    for (int i = start + grp; i < end; i += 4) {
        int s = g_csrc[i];
        m = fmaxf(m, leaky(g_as1[s * 8 + h] + adv));
    }
    m = fmaxf(m, __shfl_xor_sync(0xffffffffu, m, 8));
    m = fmaxf(m, __shfl_xor_sync(0xffffffffu, m, 16));

    // pass 2: exp + fp16 float4 gather, 2 edges per iteration (MLP=2)
    float2 acc4[4];
#pragma unroll
    for (int q = 0; q < 4; q++) acc4[q] = make_float2(0.f, 0.f);
    float z = 0.f;
    const int hsel = lane >> 2;
    int i = start;
    for (; i + 1 < end; i += 2) {
        int sA = g_csrc[i];
        int sB = g_csrc[i + 1];
        float pA = 0.f, pB = 0.f;
        if (lane < 8) {
            pA = __expf(leaky(g_as1[sA * 8 + lane] + adv) - m);
            pB = __expf(leaky(g_as1[sB * 8 + lane] + adv) - m);
            z += pA + pB;
        }
        float4 rawA = *(const float4*)&g_xp1h[(long)sA * C1 + 8 * lane];
        float4 rawB = *(const float4*)&g_xp1h[(long)sB * C1 + 8 * lane];
        float phA = __shfl_sync(0xffffffffu, pA, hsel);
        float phB = __shfl_sync(0xffffffffu, pB, hsel);
        const __half2* hpA = reinterpret_cast<const __half2*>(&rawA);
        const __half2* hpB = reinterpret_cast<const __half2*>(&rawB);
#pragma unroll
        for (int q = 0; q < 4; q++) {
            float2 fA = __half22float2(hpA[q]);
            float2 fB = __half22float2(hpB[q]);
            acc4[q].x += phA * fA.x + phB * fB.x;
            acc4[q].y += phA * fA.y + phB * fB.y;
        }
    }
    if (i < end) {
        int s = g_csrc[i];
        float p = 0.f;
        if (lane < 8) {
            p = __expf(leaky(g_as1[s * 8 + lane] + adv) - m);
            z += p;
        }
        float4 raw = *(const float4*)&g_xp1h[(long)s * C1 + 8 * lane];
        float ph = __shfl_sync(0xffffffffu, p, hsel);
        const __half2* hp = reinterpret_cast<const __half2*>(&raw);
#pragma unroll
        for (int q = 0; q < 4; q++) {
            float2 f = __half22float2(hp[q]);
            acc4[q].x += ph * f.x;
            acc4[q].y += ph * f.y;
        }
    }

    // finalize: divide, bias, relu -> fp16 g_hh
    float zh = __shfl_sync(0xffffffffu, z, hsel);
    float zi = 1.0f / (zh + 1e-16f);
    int ch = 8 * lane;
    float o[8];
    o[0] = fmaxf(acc4[0].x * zi + b1[ch + 0], 0.f);
    o[1] = fmaxf(acc4[0].y * zi + b1[ch + 1], 0.f);
    o[2] = fmaxf(acc4[1].x * zi + b1[ch + 2], 0.f);
    o[3] = fmaxf(acc4[1].y * zi + b1[ch + 3], 0.f);
    o[4] = fmaxf(acc4[2].x * zi + b1[ch + 4], 0.f);
    o[5] = fmaxf(acc4[2].y * zi + b1[ch + 5], 0.f);
    o[6] = fmaxf(acc4[3].x * zi + b1[ch + 6], 0.f);
    o[7] = fmaxf(acc4[3].y * zi + b1[ch + 7], 0.f);
    __half2 q0 = __floats2half2_rn(o[0], o[1]);
    __half2 q1 = __floats2half2_rn(o[2], o[3]);
    __half2 q2 = __floats2half2_rn(o[4], o[5]);
    __half2 q3 = __floats2half2_rn(o[6], o[7]);
    uint4 pack;
    pack.x = *(unsigned*)&q0; pack.y = *(unsigned*)&q1;
    pack.z = *(unsigned*)&q2; pack.w = *(unsigned*)&q3;
    *(uint4*)&g_hh[(long)n * C1 + ch] = pack;
}

// ---------- layer-2 aggregation (two-pass, unroll-2) + log_softmax ----------
__global__ __launch_bounds__(256) void agg2_kernel(const float* __restrict__ b2,
                                                   float* __restrict__ out) {
    int n = (blockIdx.x * blockDim.x + threadIdx.x) >> 5;
    int lane = threadIdx.x & 31;
    if (n >= N_NODES) return;
    const int start = g_rowstart[n];
    const int end   = g_rowstart[n + 1];
    const float adn = g_ad2[n];

    float m = -INFINITY;
    for (int i = start + lane; i < end; i += 32)
        m = fmaxf(m, leaky(g_as2[g_csrc[i]] + adn));
#pragma unroll
    for (int o = 16; o > 0; o >>= 1)
        m = fmaxf(m, __shfl_xor_sync(0xffffffffu, m, o));

    float4 a = make_float4(0.f, 0.f, 0.f, 0.f);
    float z = 0.f;
    int i = start;
    for (; i + 1 < end; i += 2) {
        int sA = g_csrc[i];
        int sB = g_csrc[i + 1];
        float pA = __expf(leaky(g_as2[sA] + adn) - m);
        float pB = __expf(leaky(g_as2[sB] + adn) - m);
        z += pA + pB;
        if (lane < 10) {
            float2 rawA = *(const float2*)&g_xp2h[(long)sA * OUT_CH + 4 * lane];
            float2 rawB = *(const float2*)&g_xp2h[(long)sB * OUT_CH + 4 * lane];
            const __half2* hpA = reinterpret_cast<const __half2*>(&rawA);
            const __half2* hpB = reinterpret_cast<const __half2*>(&rawB);
            float2 fA0 = __half22float2(hpA[0]), fA1 = __half22float2(hpA[1]);
            float2 fB0 = __half22float2(hpB[0]), fB1 = __half22float2(hpB[1]);
            a.x += pA * fA0.x + pB * fB0.x;
            a.y += pA * fA0.y + pB * fB0.y;
            a.z += pA * fA1.x + pB * fB1.x;
            a.w += pA * fA1.y + pB * fB1.y;
        }
    }
    if (i < end) {
        int s = g_csrc[i];
        float p = __expf(leaky(g_as2[s] + adn) - m);
        z += p;
        if (lane < 10) {
            float2 raw = *(const float2*)&g_xp2h[(long)s * OUT_CH + 4 * lane];
            const __half2* hp = reinterpret_cast<const __half2*>(&raw);
            float2 f0 = __half22float2(hp[0]);
            float2 f1 = __half22float2(hp[1]);
            a.x += p * f0.x; a.y += p * f0.y; a.z += p * f1.x; a.w += p * f1.y;
        }
    }
    float zi = 1.0f / (z + 1e-16f);

    float x0 = -INFINITY, x1 = -INFINITY, x2 = -INFINITY, x3 = -INFINITY;
    if (lane < 10) {
        int ch = 4 * lane;
        x0 = a.x * zi + b2[ch + 0];
        x1 = a.y * zi + b2[ch + 1];
        x2 = a.z * zi + b2[ch + 2];
        x3 = a.w * zi + b2[ch + 3];
    }
    float mx = fmaxf(fmaxf(x0, x1), fmaxf(x2, x3));
#pragma unroll
    for (int o = 16; o > 0; o >>= 1) mx = fmaxf(mx, __shfl_xor_sync(0xffffffffu, mx, o));
    float se = 0.f;
    if (lane < 10)
        se = __expf(x0 - mx) + __expf(x1 - mx) + __expf(x2 - mx) + __expf(x3 - mx);
#pragma unroll
    for (int o = 16; o > 0; o >>= 1) se += __shfl_xor_sync(0xffffffffu, se, o);
    float lse = mx + logf(se);
    if (lane < 10) {
        float4 o4 = make_float4(x0 - lse, x1 - lse, x2 - lse, x3 - lse);
        *(float4*)&out[(long)n * OUT_CH + 4 * lane] = o4;
    }
}

// ---------------- launch ----------------------------------------------------
extern "C" void kernel_launch(void* const* d_in, const int* in_sizes, int n_in,
                              void* d_out, int out_size) {
    const float* x        = (const float*)d_in[0];
    const int*   ei       = (const int*)d_in[1];
    const float* W1       = (const float*)d_in[2];
    const float* att_src1 = (const float*)d_in[3];
    const float* att_dst1 = (const float*)d_in[4];
    const float* b1       = (const float*)d_in[5];
    const float* W2       = (const float*)d_in[6];
    const float* att_src2 = (const float*)d_in[7];
    const float* att_dst2 = (const float*)d_in[8];
    const float* b2       = (const float*)d_in[9];
    float*       out      = (float*)d_out;

    // Fork: CSR build on side stream, concurrent with GEMM1 on main stream.
    cudaEventRecord(g_ss.fork, 0);
    cudaStreamWaitEvent(g_ss.s, g_ss.fork, 0);

    zero_kernel<<<(N_NODES + 255) / 256, 256, 0, g_ss.s>>>();
    hist_kernel<<<(ET + 255) / 256, 256, 0, g_ss.s>>>(ei);
    scan_kernel<<<1, 1024, 0, g_ss.s>>>();
    scatter_kernel<<<(ET + 255) / 256, 256, 0, g_ss.s>>>(ei);
    cudaEventRecord(g_ss.join, g_ss.s);

    // layer-1 GEMM (independent of CSR)
    {
        dim3 grid(C1 / 128, (N_NODES + 127) / 128);
        sgemm1_tc_kernel<<<grid, 256>>>(x, W1, att_src1, att_dst1, N_NODES);
    }

    // Join: aggregation needs both CSR and GEMM1.
    cudaStreamWaitEvent(0, g_ss.join, 0);
    agg1_kernel<<<(N_NODES * 32 + 255) / 256, 256>>>(b1);

    // layer 2
    sgemm2_tc_kernel<<<(N_NODES + 127) / 128, 256>>>(W2, att_src2, att_dst2, N_NODES);
    agg2_kernel<<<(N_NODES * 32 + 255) / 256, 256>>>(b2, out);
}

// round 16
// speedup vs baseline: 1.2599x; 1.1645x over previous
#include <cuda_runtime.h>
#include <cuda_fp16.h>
#include <math.h>

#define N_NODES 100000
#define E_EDGES 800000
#define ET (E_EDGES + N_NODES)   // edges + self loops = 900000
#define IN_CH 128
#define HID 32
#define HEADS 8
#define C1 (HEADS * HID)          // 256
#define OUT_CH 40
#define NEG_SLOPE 0.2f

// ---------------- scratch (device globals; no allocation allowed) ----------
__device__ __half g_xp1h[N_NODES * C1];     // fp16 xp1
__device__ __half g_hh[N_NODES * C1];       // fp16 h (layer-1 output)
__device__ __half g_xp2h[N_NODES * OUT_CH]; // fp16 xp2
__device__ float  g_as1[N_NODES * HEADS];
__device__ float  g_ad1[N_NODES * HEADS];
__device__ float  g_as2[N_NODES];
__device__ float  g_ad2[N_NODES];

__device__ int g_deg[N_NODES];
__device__ int g_rowstart[N_NODES + 1];
__device__ int g_cursor[N_NODES];
__device__ int g_csrc[ET];

__device__ __forceinline__ float leaky(float x) {
    return x > 0.0f ? x : NEG_SLOPE * x;
}

// ---- side-stream handles (created at load time; identical work per call) --
struct SideStream {
    cudaStream_t s;
    cudaEvent_t  fork, join;
    SideStream() {
        cudaStreamCreateWithFlags(&s, cudaStreamNonBlocking);
        cudaEventCreateWithFlags(&fork, cudaEventDisableTiming);
        cudaEventCreateWithFlags(&join, cudaEventDisableTiming);
    }
};
static SideStream g_ss;

// ================= CSR build ================================================
__global__ void zero_kernel() {
    int i = blockIdx.x * blockDim.x + threadIdx.x;
    if (i < N_NODES) g_deg[i] = 0;
}

__global__ void hist_kernel(const int* __restrict__ ei) {
    int e = blockIdx.x * blockDim.x + threadIdx.x;
    if (e >= ET) return;
    int dst = (e < E_EDGES) ? ei[E_EDGES + e] : e - E_EDGES;
    atomicAdd(&g_deg[dst], 1);
}

__global__ void scan_kernel() {
    __shared__ int sums[1024];
    const int t = threadIdx.x;
    const int CH = (N_NODES + 1023) / 1024;
    int lo = t * CH;
    int hi = lo + CH; if (hi > N_NODES) hi = N_NODES;
    int s = 0;
    for (int i = lo; i < hi; i++) s += g_deg[i];
    sums[t] = s;
    __syncthreads();
    for (int o = 1; o < 1024; o <<= 1) {
        int u = (t >= o) ? sums[t - o] : 0;
        __syncthreads();
        sums[t] += u;
        __syncthreads();
    }
    int run = sums[t] - s;
    for (int i = lo; i < hi; i++) {
        g_rowstart[i] = run;
        g_cursor[i]   = run;
        run += g_deg[i];
    }
    if (t == 0) g_rowstart[N_NODES] = ET;
}

__global__ void scatter_kernel(const int* __restrict__ ei) {
    int e = blockIdx.x * blockDim.x + threadIdx.x;
    if (e >= ET) return;
    int src, dst;
    if (e < E_EDGES) { src = ei[e]; dst = ei[E_EDGES + e]; }
    else             { src = dst = e - E_EDGES; }
    int pos = atomicAdd(&g_cursor[dst], 1);
    g_csrc[pos] = src;
}

// ================= fp16 helpers =============================================
__device__ __forceinline__ void h_split(float x, __half& hi, __half& lo) {
    hi = __float2half_rn(x);
    lo = __float2half_rn(x - __half2float(hi));
}
__device__ __forceinline__ void mma_f16(float* d, const unsigned* a, const unsigned* b) {
    asm volatile(
        "mma.sync.aligned.m16n8k16.row.col.f32.f16.f16.f32 "
        "{%0,%1,%2,%3}, {%4,%5,%6,%7}, {%8,%9}, {%0,%1,%2,%3};"
        : "+f"(d[0]), "+f"(d[1]), "+f"(d[2]), "+f"(d[3])
        : "r"(a[0]), "r"(a[1]), "r"(a[2]), "r"(a[3]), "r"(b[0]), "r"(b[1]));
}
__device__ __forceinline__ float quad_reduce(float v) {
    v += __shfl_xor_sync(0xffffffffu, v, 1);
    v += __shfl_xor_sync(0xffffffffu, v, 2);
    return v;
}
__device__ __forceinline__ unsigned u32_of(__half2 v) {
    return *reinterpret_cast<unsigned*>(&v);
}

#define PAD 136

// ============ GEMM1 (fp16x3 tc) + fused attn1 dots, fp16 output =============
// BM=128, BN=128, BK=16, 256 threads (8 warps 4x2), warp tile 32x64.
// smem holds k-paired half2: As2[k2][m] = (k=2*k2, 2*k2+1).
__global__ __launch_bounds__(256) void sgemm1_tc_kernel(const float* __restrict__ A,
                                                        const float* __restrict__ B,
                                                        const float* __restrict__ att_src,
                                                        const float* __restrict__ att_dst,
                                                        int M) {
    __shared__ __align__(16) __half2 AsH2[2][8][PAD];
    __shared__ __align__(16) __half2 AsL2[2][8][PAD];
    __shared__ __align__(16) __half2 BsH2[2][8][PAD];
    __shared__ __align__(16) __half2 BsL2[2][8][PAD];

    const int tid  = threadIdx.x;
    const int wid  = tid >> 5;
    const int lane = tid & 31;
    const int warpM = wid & 3;
    const int warpN = wid >> 2;
    const int rowBase = blockIdx.y * 128;
    const int colBase = blockIdx.x * 128;

    const int r = lane >> 2;
    const int c = lane & 3;

    float acc[2][8][4];
#pragma unroll
    for (int i = 0; i < 2; i++)
#pragma unroll
        for (int j = 0; j < 8; j++)
#pragma unroll
            for (int q = 0; q < 4; q++) acc[i][j][q] = 0.0f;

    // A loader: 2 float4 per thread per stage (q = tid, tid+256)
    // B loader: k2 = tid>>5 (0..7), bnq = (tid&31)*4; two consecutive-k rows
    const int bk2 = tid >> 5;
    const int bnq = (tid & 31) * 4;

    float4 avv[2];
    float4 bv0, bv1;

    // ---- stage-0 load ----
#pragma unroll
    for (int t = 0; t < 2; t++) {
        int q = tid + t * 256;
        int ar = q >> 2, akg = q & 3;
        int gr = rowBase + ar;
        avv[t] = make_float4(0.f, 0.f, 0.f, 0.f);
        if (gr < M) avv[t] = *(const float4*)&A[(long)gr * IN_CH + akg * 4];
    }
    bv0 = *(const float4*)&B[(long)(2 * bk2)     * C1 + colBase + bnq];
    bv1 = *(const float4*)&B[(long)(2 * bk2 + 1) * C1 + colBase + bnq];
    {
#pragma unroll
        for (int t = 0; t < 2; t++) {
            int q = tid + t * 256;
            int ar = q >> 2, akg = q & 3;
            __half hx, lx, hy, ly, hz, lz, hw, lw;
            h_split(avv[t].x, hx, lx); h_split(avv[t].y, hy, ly);
            h_split(avv[t].z, hz, lz); h_split(avv[t].w, hw, lw);
            AsH2[0][akg * 2 + 0][ar] = __halves2half2(hx, hy);
            AsH2[0][akg * 2 + 1][ar] = __halves2half2(hz, hw);
            AsL2[0][akg * 2 + 0][ar] = __halves2half2(lx, ly);
            AsL2[0][akg * 2 + 1][ar] = __halves2half2(lz, lw);
        }
        const float* e0 = (const float*)&bv0;
        const float* e1 = (const float*)&bv1;
        __half2 hh[4], ll[4];
#pragma unroll
        for (int j = 0; j < 4; j++) {
            __half h0, l0, h1, l1;
            h_split(e0[j], h0, l0);
            h_split(e1[j], h1, l1);
            hh[j] = __halves2half2(h0, h1);
            ll[j] = __halves2half2(l0, l1);
        }
        *(uint4*)&BsH2[0][bk2][bnq] = *(uint4*)hh;
        *(uint4*)&BsL2[0][bk2][bnq] = *(uint4*)ll;
    }
    __syncthreads();

    int p = 0;
#pragma unroll
    for (int s = 0; s < 8; s++) {
        if (s < 7) {
            int k0 = (s + 1) * 16;
#pragma unroll
            for (int t = 0; t < 2; t++) {
                int q = tid + t * 256;
                int ar = q >> 2, akg = q & 3;
                int gr = rowBase + ar;
                avv[t] = make_float4(0.f, 0.f, 0.f, 0.f);
                if (gr < M) avv[t] = *(const float4*)&A[(long)gr * IN_CH + k0 + akg * 4];
            }
            bv0 = *(const float4*)&B[(long)(k0 + 2 * bk2)     * C1 + colBase + bnq];
            bv1 = *(const float4*)&B[(long)(k0 + 2 * bk2 + 1) * C1 + colBase + bnq];
        }
        // ---- compute stage p: one k16 step ----
        {
            unsigned ah[2][4], al[2][4];
#pragma unroll
            for (int im = 0; im < 2; im++) {
                int mb = warpM * 32 + im * 16;
                ah[im][0] = u32_of(AsH2[p][c][mb + r]);
                ah[im][1] = u32_of(AsH2[p][c][mb + 8 + r]);
                ah[im][2] = u32_of(AsH2[p][4 + c][mb + r]);
                ah[im][3] = u32_of(AsH2[p][4 + c][mb + 8 + r]);
                al[im][0] = u32_of(AsL2[p][c][mb + r]);
                al[im][1] = u32_of(AsL2[p][c][mb + 8 + r]);
                al[im][2] = u32_of(AsL2[p][4 + c][mb + r]);
                al[im][3] = u32_of(AsL2[p][4 + c][mb + 8 + r]);
            }
            unsigned bh[8][2], bl[8][2];
#pragma unroll
            for (int in = 0; in < 8; in++) {
                int nb = warpN * 64 + in * 8 + r;
                bh[in][0] = u32_of(BsH2[p][c][nb]);
                bh[in][1] = u32_of(BsH2[p][4 + c][nb]);
                bl[in][0] = u32_of(BsL2[p][c][nb]);
                bl[in][1] = u32_of(BsL2[p][4 + c][nb]);
            }
#pragma unroll
            for (int im = 0; im < 2; im++)
#pragma unroll
                for (int in = 0; in < 8; in++) {
                    mma_f16(acc[im][in], al[im], bh[in]);
                    mma_f16(acc[im][in], ah[im], bl[in]);
                    mma_f16(acc[im][in], ah[im], bh[in]);
                }
        }
        if (s < 7) {
            p ^= 1;
#pragma unroll
            for (int t = 0; t < 2; t++) {
                int q = tid + t * 256;
                int ar = q >> 2, akg = q & 3;
                __half hx, lx, hy, ly, hz, lz, hw, lw;
                h_split(avv[t].x, hx, lx); h_split(avv[t].y, hy, ly);
                h_split(avv[t].z, hz, lz); h_split(avv[t].w, hw, lw);
                AsH2[p][akg * 2 + 0][ar] = __halves2half2(hx, hy);
                AsH2[p][akg * 2 + 1][ar] = __halves2half2(hz, hw);
                AsL2[p][akg * 2 + 0][ar] = __halves2half2(lx, ly);
                AsL2[p][akg * 2 + 1][ar] = __halves2half2(lz, lw);
            }
            const float* e0 = (const float*)&bv0;
            const float* e1 = (const float*)&bv1;
            __half2 hh[4], ll[4];
#pragma unroll
            for (int j = 0; j < 4; j++) {
                __half h0, l0, h1, l1;
                h_split(e0[j], h0, l0);
                h_split(e1[j], h1, l1);
                hh[j] = __halves2half2(h0, h1);
                ll[j] = __halves2half2(l0, l1);
            }
            *(uint4*)&BsH2[p][bk2][bnq] = *(uint4*)hh;
            *(uint4*)&BsL2[p][bk2][bnq] = *(uint4*)ll;
            __syncthreads();
        }
    }

    // epilogue: fp16 mirror + fused attn dots (exclusive (row,head) owner)
#pragma unroll
    for (int im = 0; im < 2; im++) {
        int row0 = rowBase + warpM * 32 + im * 16 + r;
        int row1 = row0 + 8;
        float s0[2] = {0.f, 0.f}, d0[2] = {0.f, 0.f};
        float s1[2] = {0.f, 0.f}, d1[2] = {0.f, 0.f};
#pragma unroll
        for (int in = 0; in < 8; in++) {
            int col = colBase + warpN * 64 + in * 8 + 2 * c;
            float w0 = att_src[col], w1 = att_src[col + 1];
            float v0 = att_dst[col], v1 = att_dst[col + 1];
            int hp = in >> 2;
            s0[hp] += acc[im][in][0] * w0 + acc[im][in][1] * w1;
            d0[hp] += acc[im][in][0] * v0 + acc[im][in][1] * v1;
            s1[hp] += acc[im][in][2] * w0 + acc[im][in][3] * w1;
            d1[hp] += acc[im][in][2] * v0 + acc[im][in][3] * v1;
            if (row0 < M)
                *(__half2*)&g_xp1h[(long)row0 * C1 + col] =
                    __float22half2_rn(make_float2(acc[im][in][0], acc[im][in][1]));
            if (row1 < M)
                *(__half2*)&g_xp1h[(long)row1 * C1 + col] =
                    __float22half2_rn(make_float2(acc[im][in][2], acc[im][in][3]));
        }
#pragma unroll
        for (int hp = 0; hp < 2; hp++) {
            s0[hp] = quad_reduce(s0[hp]); d0[hp] = quad_reduce(d0[hp]);
            s1[hp] = quad_reduce(s1[hp]); d1[hp] = quad_reduce(d1[hp]);
        }
        if (c == 0) {
            int hbase = (colBase >> 5) + warpN * 2;
#pragma unroll
            for (int hp = 0; hp < 2; hp++) {
                if (row0 < M) {
                    g_as1[row0 * 8 + hbase + hp] = s0[hp];
                    g_ad1[row0 * 8 + hbase + hp] = d0[hp];
                }
                if (row1 < M) {
                    g_as1[row1 * 8 + hbase + hp] = s1[hp];
                    g_ad1[row1 * 8 + hbase + hp] = d1[hp];
                }
            }
        }
    }
}

// ============ GEMM2 (fp16 exact A, fp16x2 B) + fused attn2 dots =============
// BM=128, BN=40, BK=16, 256 threads; warp w owns rows w*16..w*16+15.
__global__ __launch_bounds__(256) void sgemm2_tc_kernel(const float* __restrict__ B,
                                                        const float* __restrict__ att_src,
                                                        const float* __restrict__ att_dst,
                                                        int M) {
    __shared__ __align__(16) __half2 As2[2][8][PAD];
    __shared__ __half2 BsH2[2][8][40];
    __shared__ __half2 BsL2[2][8][40];

    const int tid  = threadIdx.x;
    const int wid  = tid >> 5;
    const int lane = tid & 31;
    const int rowBase = blockIdx.x * 128;
    const int r = lane >> 2;
    const int c = lane & 3;

    float acc[5][4];
#pragma unroll
    for (int j = 0; j < 5; j++)
#pragma unroll
        for (int q = 0; q < 4; q++) acc[j][q] = 0.0f;

    // A loader: one uint4 (8 fp16 = 4 k-paired half2) per thread per stage
    const int ar  = tid >> 1;            // 0..127
    const int akq = (tid & 1) * 8;       // 0 or 8 -> k2 base 0 or 4
    const int gr  = rowBase + ar;

    uint4 araw;
    float bA[2], bB[2];

    // ---- stage-0 load ----
    araw = make_uint4(0, 0, 0, 0);
    if (gr < M) araw = *(const uint4*)&g_hh[(long)gr * C1 + akq];
#pragma unroll
    for (int t = 0; t < 2; t++) {
        int idx = tid + t * 256;
        bA[t] = 0.f; bB[t] = 0.f;
        if (idx < 8 * 40) {
            int k2 = idx / 40, n = idx % 40;
            bA[t] = B[(long)(2 * k2)     * OUT_CH + n];
            bB[t] = B[(long)(2 * k2 + 1) * OUT_CH + n];
        }
    }
    {
        const __half2* hp = reinterpret_cast<const __half2*>(&araw);
#pragma unroll
        for (int q = 0; q < 4; q++) As2[0][akq / 2 + q][ar] = hp[q];
#pragma unroll
        for (int t = 0; t < 2; t++) {
            int idx = tid + t * 256;
            if (idx < 8 * 40) {
                int k2 = idx / 40, n = idx % 40;
                __half hA, lA, hB, lB;
                h_split(bA[t], hA, lA);
                h_split(bB[t], hB, lB);
                BsH2[0][k2][n] = __halves2half2(hA, hB);
                BsL2[0][k2][n] = __halves2half2(lA, lB);
            }
        }
    }
    __syncthreads();

    int p = 0;
#pragma unroll
    for (int s = 0; s < 16; s++) {
        if (s < 15) {
            int k0 = (s + 1) * 16;
            araw = make_uint4(0, 0, 0, 0);
            if (gr < M) araw = *(const uint4*)&g_hh[(long)gr * C1 + k0 + akq];
#pragma unroll
            for (int t = 0; t < 2; t++) {
                int idx = tid + t * 256;
                bA[t] = 0.f; bB[t] = 0.f;
                if (idx < 8 * 40) {
                    int k2 = idx / 40, n = idx % 40;
                    bA[t] = B[(long)(k0 + 2 * k2)     * OUT_CH + n];
                    bB[t] = B[(long)(k0 + 2 * k2 + 1) * OUT_CH + n];
                }
            }
        }
        // ---- compute stage p: one k16 step, A exact fp16 ----
        {
            unsigned a[4];
            int mb = wid * 16;
            a[0] = u32_of(As2[p][c][mb + r]);
            a[1] = u32_of(As2[p][c][mb + 8 + r]);
            a[2] = u32_of(As2[p][4 + c][mb + r]);
            a[3] = u32_of(As2[p][4 + c][mb + 8 + r]);
#pragma unroll
            for (int in = 0; in < 5; in++) {
                int nb = in * 8 + r;
                unsigned bh[2], bl[2];
                bh[0] = u32_of(BsH2[p][c][nb]);
                bh[1] = u32_of(BsH2[p][4 + c][nb]);
                bl[0] = u32_of(BsL2[p][c][nb]);
                bl[1] = u32_of(BsL2[p][4 + c][nb]);
                mma_f16(acc[in], a, bl);
                mma_f16(acc[in], a, bh);
            }
        }
        if (s < 15) {
            p ^= 1;
            const __half2* hp = reinterpret_cast<const __half2*>(&araw);
#pragma unroll
            for (int q = 0; q < 4; q++) As2[p][akq / 2 + q][ar] = hp[q];
#pragma unroll
            for (int t = 0; t < 2; t++) {
                int idx = tid + t * 256;
                if (idx < 8 * 40) {
                    int k2 = idx / 40, n = idx % 40;
                    __half hA, lA, hB, lB;
                    h_split(bA[t], hA, lA);
                    h_split(bB[t], hB, lB);
                    BsH2[p][k2][n] = __halves2half2(hA, hB);
                    BsL2[p][k2][n] = __halves2half2(lA, lB);
                }
            }
            __syncthreads();
        }
    }

    // epilogue: fp16 mirror + fused attn2 dots
    {
        int row0 = rowBase + wid * 16 + r;
        int row1 = row0 + 8;
        float s0 = 0.f, d0 = 0.f, s1 = 0.f, d1 = 0.f;
#pragma unroll
        for (int in = 0; in < 5; in++) {
            int col = in * 8 + 2 * c;
            float w0 = att_src[col], w1 = att_src[col + 1];
            float v0 = att_dst[col], v1 = att_dst[col + 1];
            s0 += acc[in][0] * w0 + acc[in][1] * w1;
            d0 += acc[in][0] * v0 + acc[in][1] * v1;
            s1 += acc[in][2] * w0 + acc[in][3] * w1;
            d1 += acc[in][2] * v0 + acc[in][3] * v1;
            if (row0 < M)
                *(__half2*)&g_xp2h[(long)row0 * OUT_CH + col] =
                    __float22half2_rn(make_float2(acc[in][0], acc[in][1]));
            if (row1 < M)
                *(__half2*)&g_xp2h[(long)row1 * OUT_CH + col] =
                    __float22half2_rn(make_float2(acc[in][2], acc[in][3]));
        }
        s0 = quad_reduce(s0); d0 = quad_reduce(d0);
        s1 = quad_reduce(s1); d1 = quad_reduce(d1);
        if (c == 0) {
            if (row0 < M) { g_as2[row0] = s0; g_ad2[row0] = d0; }
            if (row1 < M) { g_as2[row1] = s1; g_ad2[row1] = d1; }
        }
    }
}

// ------- layer-1 aggregation: two-pass, unroll-2 fp16 gather, fp16 out ------
__global__ __launch_bounds__(256) void agg1_kernel(const float* __restrict__ b1) {
    int n = (blockIdx.x * blockDim.x + threadIdx.x) >> 5;
    int lane = threadIdx.x & 31;
    if (n >= N_NODES) return;
    const int start = g_rowstart[n];
    const int end   = g_rowstart[n + 1];

    const int h   = lane & 7;
    const int grp = lane >> 3;
    const float adv = g_ad1[n * 8 + h];

    // pass 1: per-head max
    float m = -INFINITY;
    for (int i = start + grp; i < end; i += 4) {
        int s = g_csrc[i];
        m = fmaxf(m, leaky(g_as1[s * 8 + h] + adv));
    }
    m = fmaxf(m, __shfl_xor_sync(0xffffffffu, m, 8));
    m = fmaxf(m, __shfl_xor_sync(0xffffffffu, m, 16));

    // pass 2: exp + fp16 float4 gather, 2 edges per iteration (MLP=2)
    float2 acc4[4];
#pragma unroll
    for (int q = 0; q < 4; q++) acc4[q] = make_float2(0.f, 0.f);
    float z = 0.f;
    const int hsel = lane >> 2;
    int i = start;
    for (; i + 1 < end; i += 2) {
        int sA = g_csrc[i];
        int sB = g_csrc[i + 1];
        float pA = 0.f, pB = 0.f;
        if (lane < 8) {
            pA = __expf(leaky(g_as1[sA * 8 + lane] + adv) - m);
            pB = __expf(leaky(g_as1[sB * 8 + lane] + adv) - m);
            z += pA + pB;
        }
        float4 rawA = *(const float4*)&g_xp1h[(long)sA * C1 + 8 * lane];
        float4 rawB = *(const float4*)&g_xp1h[(long)sB * C1 + 8 * lane];
        float phA = __shfl_sync(0xffffffffu, pA, hsel);
        float phB = __shfl_sync(0xffffffffu, pB, hsel);
        const __half2* hpA = reinterpret_cast<const __half2*>(&rawA);
        const __half2* hpB = reinterpret_cast<const __half2*>(&rawB);
#pragma unroll
        for (int q = 0; q < 4; q++) {
            float2 fA = __half22float2(hpA[q]);
            float2 fB = __half22float2(hpB[q]);
            acc4[q].x += phA * fA.x + phB * fB.x;
            acc4[q].y += phA * fA.y + phB * fB.y;
        }
    }
    if (i < end) {
        int s = g_csrc[i];
        float p = 0.f;
        if (lane < 8) {
            p = __expf(leaky(g_as1[s * 8 + lane] + adv) - m);
            z += p;
        }
        float4 raw = *(const float4*)&g_xp1h[(long)s * C1 + 8 * lane];
        float ph = __shfl_sync(0xffffffffu, p, hsel);
        const __half2* hp = reinterpret_cast<const __half2*>(&raw);
#pragma unroll
        for (int q = 0; q < 4; q++) {
            float2 f = __half22float2(hp[q]);
            acc4[q].x += ph * f.x;
            acc4[q].y += ph * f.y;
        }
    }

    // finalize: divide, bias, relu -> fp16 g_hh
    float zh = __shfl_sync(0xffffffffu, z, hsel);
    float zi = 1.0f / (zh + 1e-16f);
    int ch = 8 * lane;
    float o[8];
    o[0] = fmaxf(acc4[0].x * zi + b1[ch + 0], 0.f);
    o[1] = fmaxf(acc4[0].y * zi + b1[ch + 1], 0.f);
    o[2] = fmaxf(acc4[1].x * zi + b1[ch + 2], 0.f);
    o[3] = fmaxf(acc4[1].y * zi + b1[ch + 3], 0.f);
    o[4] = fmaxf(acc4[2].x * zi + b1[ch + 4], 0.f);
    o[5] = fmaxf(acc4[2].y * zi + b1[ch + 5], 0.f);
    o[6] = fmaxf(acc4[3].x * zi + b1[ch + 6], 0.f);
    o[7] = fmaxf(acc4[3].y * zi + b1[ch + 7], 0.f);
    __half2 q0 = __floats2half2_rn(o[0], o[1]);
    __half2 q1 = __floats2half2_rn(o[2], o[3]);
    __half2 q2 = __floats2half2_rn(o[4], o[5]);
    __half2 q3 = __floats2half2_rn(o[6], o[7]);
    uint4 pack;
    pack.x = *(unsigned*)&q0; pack.y = *(unsigned*)&q1;
    pack.z = *(unsigned*)&q2; pack.w = *(unsigned*)&q3;
    *(uint4*)&g_hh[(long)n * C1 + ch] = pack;
}

// ---------- layer-2 aggregation (two-pass, unroll-2) + log_softmax ----------
__global__ __launch_bounds__(256) void agg2_kernel(const float* __restrict__ b2,
                                                   float* __restrict__ out) {
    int n = (blockIdx.x * blockDim.x + threadIdx.x) >> 5;
    int lane = threadIdx.x & 31;
    if (n >= N_NODES) return;
    const int start = g_rowstart[n];
    const int end   = g_rowstart[n + 1];
    const float adn = g_ad2[n];

    float m = -INFINITY;
    for (int i = start + lane; i < end; i += 32)
        m = fmaxf(m, leaky(g_as2[g_csrc[i]] + adn));
#pragma unroll
    for (int o = 16; o > 0; o >>= 1)
        m = fmaxf(m, __shfl_xor_sync(0xffffffffu, m, o));

    float4 a = make_float4(0.f, 0.f, 0.f, 0.f);
    float z = 0.f;
    int i = start;
    for (; i + 1 < end; i += 2) {
        int sA = g_csrc[i];
        int sB = g_csrc[i + 1];
        float pA = __expf(leaky(g_as2[sA] + adn) - m);
        float pB = __expf(leaky(g_as2[sB] + adn) - m);
        z += pA + pB;
        if (lane < 10) {
            float2 rawA = *(const float2*)&g_xp2h[(long)sA * OUT_CH + 4 * lane];
            float2 rawB = *(const float2*)&g_xp2h[(long)sB * OUT_CH + 4 * lane];
            const __half2* hpA = reinterpret_cast<const __half2*>(&rawA);
            const __half2* hpB = reinterpret_cast<const __half2*>(&rawB);
            float2 fA0 = __half22float2(hpA[0]), fA1 = __half22float2(hpA[1]);
            float2 fB0 = __half22float2(hpB[0]), fB1 = __half22float2(hpB[1]);
            a.x += pA * fA0.x + pB * fB0.x;
            a.y += pA * fA0.y + pB * fB0.y;
            a.z += pA * fA1.x + pB * fB1.x;
            a.w += pA * fA1.y + pB * fB1.y;
        }
    }
    if (i < end) {
        int s = g_csrc[i];
        float p = __expf(leaky(g_as2[s] + adn) - m);
        z += p;
        if (lane < 10) {
            float2 raw = *(const float2*)&g_xp2h[(long)s * OUT_CH + 4 * lane];
            const __half2* hp = reinterpret_cast<const __half2*>(&raw);
            float2 f0 = __half22float2(hp[0]);
            float2 f1 = __half22float2(hp[1]);
            a.x += p * f0.x; a.y += p * f0.y; a.z += p * f1.x; a.w += p * f1.y;
        }
    }
    float zi = 1.0f / (z + 1e-16f);

    float x0 = -INFINITY, x1 = -INFINITY, x2 = -INFINITY, x3 = -INFINITY;
    if (lane < 10) {
        int ch = 4 * lane;
        x0 = a.x * zi + b2[ch + 0];
        x1 = a.y * zi + b2[ch + 1];
        x2 = a.z * zi + b2[ch + 2];
        x3 = a.w * zi + b2[ch + 3];
    }
    float mx = fmaxf(fmaxf(x0, x1), fmaxf(x2, x3));
#pragma unroll
    for (int o = 16; o > 0; o >>= 1) mx = fmaxf(mx, __shfl_xor_sync(0xffffffffu, mx, o));
    float se = 0.f;
    if (lane < 10)
        se = __expf(x0 - mx) + __expf(x1 - mx) + __expf(x2 - mx) + __expf(x3 - mx);
#pragma unroll
    for (int o = 16; o > 0; o >>= 1) se += __shfl_xor_sync(0xffffffffu, se, o);
    float lse = mx + logf(se);
    if (lane < 10) {
        float4 o4 = make_float4(x0 - lse, x1 - lse, x2 - lse, x3 - lse);
        *(float4*)&out[(long)n * OUT_CH + 4 * lane] = o4;
    }
}

// ---------------- launch ----------------------------------------------------
extern "C" void kernel_launch(void* const* d_in, const int* in_sizes, int n_in,
                              void* d_out, int out_size) {
    const float* x        = (const float*)d_in[0];
    const int*   ei       = (const int*)d_in[1];
    const float* W1       = (const float*)d_in[2];
    const float* att_src1 = (const float*)d_in[3];
    const float* att_dst1 = (const float*)d_in[4];
    const float* b1       = (const float*)d_in[5];
    const float* W2       = (const float*)d_in[6];
    const float* att_src2 = (const float*)d_in[7];
    const float* att_dst2 = (const float*)d_in[8];
    const float* b2       = (const float*)d_in[9];
    float*       out      = (float*)d_out;

    // Fork: CSR build on side stream, concurrent with GEMM1 tail.
    cudaEventRecord(g_ss.fork, 0);
    cudaStreamWaitEvent(g_ss.s, g_ss.fork, 0);

    zero_kernel<<<(N_NODES + 255) / 256, 256, 0, g_ss.s>>>();
    hist_kernel<<<(ET + 255) / 256, 256, 0, g_ss.s>>>(ei);
    scan_kernel<<<1, 1024, 0, g_ss.s>>>();
    scatter_kernel<<<(ET + 255) / 256, 256, 0, g_ss.s>>>(ei);
    cudaEventRecord(g_ss.join, g_ss.s);

    // layer-1 GEMM (independent of CSR)
    {
        dim3 grid(C1 / 128, (N_NODES + 127) / 128);
        sgemm1_tc_kernel<<<grid, 256>>>(x, W1, att_src1, att_dst1, N_NODES);
    }

    // Join: aggregation needs both CSR and GEMM1.
    cudaStreamWaitEvent(0, g_ss.join, 0);
    agg1_kernel<<<(N_NODES * 32 + 255) / 256, 256>>>(b1);

    // layer 2
    sgemm2_tc_kernel<<<(N_NODES + 127) / 128, 256>>>(W2, att_src2, att_dst2, N_NODES);
    agg2_kernel<<<(N_NODES * 32 + 255) / 256, 256>>>(b2, out);
}